// round 1
// baseline (speedup 1.0000x reference)
#include <cuda_runtime.h>
#include <math.h>

#define B_SZ 2
#define SEQ 4162
#define DM 1024
#define DI 2048
#define DSTATE 64
#define HD 128
#define NH 16
#define NL 4
#define CONV_DIM 2176
#define DIP 4240
#define MR (B_SZ*SEQ)          // 8324 rows
#define NPIX (B_SZ*4096)       // 8192
#define YHAT_ELEMS (NPIX*3)    // 24576

// ---------------- scratch (static device allocations; no cudaMalloc) -------
__device__ float g_x[(size_t)MR*DM];        // residual stream
__device__ float g_ln[(size_t)MR*DM];       // layernorm output
__device__ float g_zx[(size_t)MR*DIP];      // in_proj output
__device__ float g_xBC[(size_t)MR*CONV_DIM];// conv+silu output
__device__ float g_y[(size_t)MR*DI];        // scan output / gated / rmsnorm
__device__ float g_dt[MR*NH];
__device__ float g_dA[MR*NH];
__device__ float g_h8[B_SZ*64*DM];
__device__ float g_part[NPIX];

// ---------------- helpers ---------------------------------------------------
__device__ __forceinline__ float siluf(float x) { return x / (1.f + expf(-x)); }

__device__ __forceinline__ float blockSum256(float v, float* red) {
    int tid = threadIdx.x;
    red[tid] = v;
    __syncthreads();
#pragma unroll
    for (int s = 128; s > 0; s >>= 1) {
        if (tid < s) red[tid] += red[tid + s];
        __syncthreads();
    }
    float r = red[0];
    __syncthreads();
    return r;
}

// ---------------- stage 0: embed -------------------------------------------
__global__ void k_h8(const float* __restrict__ im8, const float* __restrict__ w,
                     const float* __restrict__ b) {
    int idx = blockIdx.x * blockDim.x + threadIdx.x;
    if (idx >= B_SZ * 64 * DM) return;
    int d = idx % DM;
    int r = idx / DM;  // b*64 + i
    const float* p = im8 + r * 3;
    g_h8[idx] = p[0] * w[d] + p[1] * w[DM + d] + p[2] * w[2 * DM + d] + b[d];
}

__global__ void k_assemble(const float* __restrict__ s0, const float* __restrict__ s1,
                           const float* __restrict__ posemb) {
    int idx = blockIdx.x * blockDim.x + threadIdx.x;
    if (idx >= MR * DM) return;
    int d = idx % DM;
    int t = (idx / DM) % SEQ;
    int b = idx / (DM * SEQ);
    float v;
    if (t == 0) v = s0[d];
    else if (t <= 64) v = g_h8[(b * 64 + t - 1) * DM + d];
    else if (t == 65) v = s1[d];
    else {
        int p = t - 66;
        int src = ((p >> 6) >> 3) * 8 + ((p & 63) >> 3);
        v = g_h8[(b * 64 + src) * DM + d] + posemb[(size_t)p * DM + d];
    }
    g_x[idx] = v;
}

// ---------------- layernorm -------------------------------------------------
__global__ void k_ln(const float* __restrict__ lnw, const float* __restrict__ lnb) {
    __shared__ float sh[DM];
    __shared__ float red[256];
    int row = blockIdx.x;
    const float* xr = g_x + (size_t)row * DM;
    float s = 0.f;
    for (int i = threadIdx.x; i < DM; i += 256) { float v = xr[i]; sh[i] = v; s += v; }
    float mean = blockSum256(s, red) * (1.f / DM);
    float vs = 0.f;
    for (int i = threadIdx.x; i < DM; i += 256) { float d = sh[i] - mean; vs += d * d; }
    float var = blockSum256(vs, red) * (1.f / DM);
    float inv = rsqrtf(var + 1e-5f);
    float* o = g_ln + (size_t)row * DM;
    for (int i = threadIdx.x; i < DM; i += 256)
        o[i] = (sh[i] - mean) * inv * lnw[i] + lnb[i];
}

// ---------------- GEMM: C[M,N] (+)= A[M,K] * B[N,K]^T ----------------------
__global__ void k_gemm(const float* __restrict__ A, const float* __restrict__ Bm,
                       float* __restrict__ C, int M, int N, int K, int accum) {
    __shared__ float As[16][65];
    __shared__ float Bs[16][65];
    int row0 = blockIdx.y * 64, col0 = blockIdx.x * 64;
    int tx = threadIdx.x & 15, ty = threadIdx.x >> 4;
    int lk = threadIdx.x & 15, lm = threadIdx.x >> 4;
    float acc[4][4] = {};
    for (int k0 = 0; k0 < K; k0 += 16) {
#pragma unroll
        for (int pp = 0; pp < 4; pp++) {
            int m = lm + pp * 16;
            int gr = row0 + m;
            As[lk][m] = (gr < M) ? A[(size_t)gr * K + k0 + lk] : 0.f;
            int gc = col0 + m;
            Bs[lk][m] = (gc < N) ? Bm[(size_t)gc * K + k0 + lk] : 0.f;
        }
        __syncthreads();
#pragma unroll
        for (int k = 0; k < 16; k++) {
            float a[4], bb[4];
#pragma unroll
            for (int i = 0; i < 4; i++) a[i] = As[k][ty * 4 + i];
#pragma unroll
            for (int j = 0; j < 4; j++) bb[j] = Bs[k][tx * 4 + j];
#pragma unroll
            for (int i = 0; i < 4; i++)
#pragma unroll
                for (int j = 0; j < 4; j++) acc[i][j] += a[i] * bb[j];
        }
        __syncthreads();
    }
#pragma unroll
    for (int i = 0; i < 4; i++) {
        int r = row0 + ty * 4 + i;
        if (r >= M) continue;
#pragma unroll
        for (int j = 0; j < 4; j++) {
            int c = col0 + tx * 4 + j;
            if (c >= N) continue;
            size_t o = (size_t)r * N + c;
            C[o] = accum ? (C[o] + acc[i][j]) : acc[i][j];
        }
    }
}

// ---------------- dt / dA ---------------------------------------------------
__global__ void k_dt(const float* __restrict__ dtb, const float* __restrict__ Alog) {
    int idx = blockIdx.x * blockDim.x + threadIdx.x;
    if (idx >= MR * NH) return;
    int h = idx % NH;
    int row = idx / NH;
    float v = g_zx[(size_t)row * DIP + (DIP - NH) + h] + dtb[h];
    float sp = (v > 20.f) ? v : log1pf(expf(v));
    float A = -expf(Alog[h]);
    g_dt[idx] = sp;
    g_dA[idx] = expf(sp * A);
}

// ---------------- causal depthwise conv (k=4) + silu ------------------------
__global__ void k_conv(const float* __restrict__ cw, const float* __restrict__ cb) {
    int idx = blockIdx.x * blockDim.x + threadIdx.x;
    if (idx >= MR * CONV_DIM) return;
    int c = idx % CONV_DIM;
    int rt = idx / CONV_DIM;
    int t = rt % SEQ;
    int b = rt / SEQ;
    const float4 w = *(const float4*)(cw + c * 4);
    const float wj[4] = {w.x, w.y, w.z, w.w};
    float acc = cb[c];
#pragma unroll
    for (int j = 0; j < 4; j++) {
        int ts = t - 3 + j;
        if (ts >= 0) acc += g_zx[((size_t)(b * SEQ + ts)) * DIP + DI + c] * wj[j];
    }
    g_xBC[idx] = siluf(acc);
}

// ---------------- selective scan --------------------------------------------
#define CHK 64
__global__ void k_scan(const float* __restrict__ Dp) {
    __shared__ float sx[CHK][32];
    __shared__ float sB[CHK][64];
    __shared__ float sC[CHK][64];
    __shared__ float sdA[CHK];
    __shared__ float sdt[CHK];
    int pblk = blockIdx.x;   // 0..3
    int h = blockIdx.y;      // 0..15
    int b = blockIdx.z;      // 0..1
    int tid = threadIdx.x;
    int pl = tid >> 3, ng = tid & 7, n0 = ng * 8;
    int p = pblk * 32 + pl;
    float s[8];
#pragma unroll
    for (int j = 0; j < 8; j++) s[j] = 0.f;
    float Dh = Dp[h];
    size_t baseRow = (size_t)b * SEQ;
    int xoff = h * HD + pblk * 32;
    for (int t0 = 0; t0 < SEQ; t0 += CHK) {
        int cnt = min(CHK, SEQ - t0);
        for (int i = tid; i < cnt * 32; i += 256) {
            int q = i >> 5, ii = i & 31;
            sx[q][ii] = g_xBC[(baseRow + t0 + q) * CONV_DIM + xoff + ii];
        }
        for (int i = tid; i < cnt * 64; i += 256) {
            int q = i >> 6, ii = i & 63;
            sB[q][ii] = g_xBC[(baseRow + t0 + q) * CONV_DIM + DI + ii];
        }
        for (int i = tid; i < cnt * 64; i += 256) {
            int q = i >> 6, ii = i & 63;
            sC[q][ii] = g_xBC[(baseRow + t0 + q) * CONV_DIM + DI + DSTATE + ii];
        }
        for (int i = tid; i < cnt; i += 256) {
            sdA[i] = g_dA[(baseRow + t0 + i) * NH + h];
            sdt[i] = g_dt[(baseRow + t0 + i) * NH + h];
        }
        __syncthreads();
        for (int q = 0; q < cnt; q++) {
            float dA = sdA[q];
            float xp = sx[q][pl];
            float a = sdt[q] * xp;
            float yp = 0.f;
#pragma unroll
            for (int j = 0; j < 8; j++) {
                s[j] = s[j] * dA + a * sB[q][n0 + j];
                yp += s[j] * sC[q][n0 + j];
            }
            yp += __shfl_xor_sync(0xffffffffu, yp, 1);
            yp += __shfl_xor_sync(0xffffffffu, yp, 2);
            yp += __shfl_xor_sync(0xffffffffu, yp, 4);
            if (ng == 0)
                g_y[(baseRow + t0 + q) * DI + h * HD + p] = yp + Dh * xp;
        }
        __syncthreads();
    }
}

// ---------------- gate (silu(z)) + RMSNorm ----------------------------------
__global__ void k_gaterms(const float* __restrict__ rmsw) {
    __shared__ float sh[DI];
    __shared__ float red[256];
    int row = blockIdx.x;
    const float* zr = g_zx + (size_t)row * DIP;
    float* yr = g_y + (size_t)row * DI;
    float ss = 0.f;
    for (int i = threadIdx.x; i < DI; i += 256) {
        float z = zr[i];
        float g = yr[i] * siluf(z);
        sh[i] = g;
        ss += g * g;
    }
    float tot = blockSum256(ss, red);
    float inv = rsqrtf(tot * (1.f / DI) + 1e-5f);
    for (int i = threadIdx.x; i < DI; i += 256)
        yr[i] = sh[i] * inv * rmsw[i];
}

// ---------------- output head + per-pixel squared error ---------------------
__global__ void k_head(const float* __restrict__ w, const float* __restrict__ bias,
                       const float* __restrict__ im64, float* __restrict__ out,
                       int out_size) {
    __shared__ float red[256];
    int r = blockIdx.x;          // 0..NPIX-1
    int b = r / 4096, p = r % 4096;
    const float* xr = g_x + ((size_t)(b * SEQ) + 66 + p) * DM;
    float a0 = 0.f, a1 = 0.f, a2 = 0.f;
    for (int i = threadIdx.x; i < DM; i += 256) {
        float v = xr[i];
        a0 += v * w[i * 3 + 0];
        a1 += v * w[i * 3 + 1];
        a2 += v * w[i * 3 + 2];
    }
    a0 = blockSum256(a0, red);
    a1 = blockSum256(a1, red);
    a2 = blockSum256(a2, red);
    if (threadIdx.x == 0) {
        float y0 = a0 + bias[0], y1 = a1 + bias[1], y2 = a2 + bias[2];
        const float* im = im64 + (size_t)r * 3;
        float e0 = y0 - im[0], e1 = y1 - im[1], e2 = y2 - im[2];
        g_part[r] = e0 * e0 + e1 * e1 + e2 * e2;
        if (out_size >= YHAT_ELEMS) {
            out[(size_t)r * 3 + 0] = y0;
            out[(size_t)r * 3 + 1] = y1;
            out[(size_t)r * 3 + 2] = y2;
        }
    }
}

__global__ void k_loss(float* __restrict__ out, int out_size) {
    __shared__ float red[256];
    float s = 0.f;
    for (int i = threadIdx.x; i < NPIX; i += 256) s += g_part[i];
    float tot = blockSum256(s, red);
    if (threadIdx.x == 0) {
        float loss = tot * (1.f / (float)YHAT_ELEMS);
        if (out_size <= 1) out[0] = loss;
        else if (out_size > YHAT_ELEMS) out[YHAT_ELEMS] = loss;
    }
}

// ---------------- driver -----------------------------------------------------
extern "C" void kernel_launch(void* const* d_in, const int* in_sizes, int n_in,
                              void* d_out, int out_size) {
    const float* im8        = (const float*)d_in[0];
    const float* im64       = (const float*)d_in[1];
    const float* from_rgb_w = (const float*)d_in[2];
    const float* from_rgb_b = (const float*)d_in[3];
    const float* to_rgb_w   = (const float*)d_in[4];
    const float* to_rgb_b   = (const float*)d_in[5];
    const float* s0         = (const float*)d_in[6];
    const float* s1         = (const float*)d_in[7];
    const float* posemb     = (const float*)d_in[8];
    const float* ln_w       = (const float*)d_in[9];
    const float* ln_b       = (const float*)d_in[10];
    const float* in_proj_w  = (const float*)d_in[11];
    const float* conv_w     = (const float*)d_in[12];
    const float* conv_b     = (const float*)d_in[13];
    const float* dt_bias    = (const float*)d_in[14];
    const float* A_log      = (const float*)d_in[15];
    const float* Dp         = (const float*)d_in[16];
    const float* rms_w      = (const float*)d_in[17];
    const float* out_proj_w = (const float*)d_in[18];
    float* out = (float*)d_out;

    float *p_x, *p_ln, *p_zx, *p_y;
    cudaGetSymbolAddress((void**)&p_x, g_x);
    cudaGetSymbolAddress((void**)&p_ln, g_ln);
    cudaGetSymbolAddress((void**)&p_zx, g_zx);
    cudaGetSymbolAddress((void**)&p_y, g_y);

    k_h8<<<(B_SZ * 64 * DM + 255) / 256, 256>>>(im8, from_rgb_w, from_rgb_b);
    k_assemble<<<(MR * DM + 255) / 256, 256>>>(s0, s1, posemb);

    for (int l = 0; l < NL; l++) {
        k_ln<<<MR, 256>>>(ln_w + l * DM, ln_b + l * DM);

        dim3 g1((DIP + 63) / 64, (MR + 63) / 64);
        k_gemm<<<g1, 256>>>(p_ln, in_proj_w + (size_t)l * DIP * DM, p_zx,
                            MR, DIP, DM, 0);

        k_dt<<<(MR * NH + 255) / 256, 256>>>(dt_bias + l * NH, A_log + l * NH);
        k_conv<<<(MR * CONV_DIM + 255) / 256, 256>>>(conv_w + l * CONV_DIM * 4,
                                                     conv_b + l * CONV_DIM);

        dim3 gs(4, NH, B_SZ);
        k_scan<<<gs, 256>>>(Dp + l * NH);

        k_gaterms<<<MR, 256>>>(rms_w + l * DI);

        dim3 g2((DM + 63) / 64, (MR + 63) / 64);
        k_gemm<<<g2, 256>>>(p_y, out_proj_w + (size_t)l * DM * DI, p_x,
                            MR, DM, DI, 1);
    }

    k_head<<<NPIX, 256>>>(to_rgb_w, to_rgb_b, im64, out, out_size);
    k_loss<<<1, 256>>>(out, out_size);
}

// round 3
// speedup vs baseline: 1.8401x; 1.8401x over previous
#include <cuda_runtime.h>
#include <math.h>
#include <stdint.h>

#define B_SZ 2
#define SEQ 4162
#define DM 1024
#define DI 2048
#define DSTATE 64
#define HD 128
#define NH 16
#define NL 4
#define CONV_DIM 2176
#define DIP 4240
#define MR (B_SZ*SEQ)          // 8324 rows
#define NPIX (B_SZ*4096)       // 8192
#define YHAT_ELEMS (NPIX*3)    // 24576

// ---------------- scratch (static device allocations; no cudaMalloc) -------
__device__ float g_x[(size_t)MR*DM];        // residual stream
__device__ float g_ln[(size_t)MR*DM];       // layernorm output
__device__ float g_zx[(size_t)MR*DIP];      // in_proj output
__device__ float g_xBC[(size_t)MR*CONV_DIM];// conv+silu output
__device__ float g_y[(size_t)MR*DI];        // scan output / gated / rmsnorm
__device__ float g_dt[MR*NH];
__device__ float g_dA[MR*NH];
__device__ float g_h8[B_SZ*64*DM];
__device__ float g_part[NPIX];

// ---------------- helpers ---------------------------------------------------
__device__ __forceinline__ float siluf(float x) { return x / (1.f + expf(-x)); }

__device__ __forceinline__ float blockSum256(float v, float* red) {
    int tid = threadIdx.x;
    red[tid] = v;
    __syncthreads();
#pragma unroll
    for (int s = 128; s > 0; s >>= 1) {
        if (tid < s) red[tid] += red[tid + s];
        __syncthreads();
    }
    float r = red[0];
    __syncthreads();
    return r;
}

__device__ __forceinline__ uint32_t f2tf32(float x) {
    uint32_t r;
    asm("cvt.rna.tf32.f32 %0, %1;" : "=r"(r) : "f"(x));
    return r;
}

// split a into tf32 hi (exact) + tf32 lo (residual)
__device__ __forceinline__ void tf32split(float a, uint32_t& hi, uint32_t& lo) {
    uint32_t ah = __float_as_uint(a) & 0xffffe000u;
    hi = ah;
    lo = f2tf32(a - __uint_as_float(ah));
}

// ---------------- stage 0: embed -------------------------------------------
__global__ void k_h8(const float* __restrict__ im8, const float* __restrict__ w,
                     const float* __restrict__ b) {
    int idx = blockIdx.x * blockDim.x + threadIdx.x;
    if (idx >= B_SZ * 64 * DM) return;
    int d = idx % DM;
    int r = idx / DM;  // b*64 + i
    const float* p = im8 + r * 3;
    g_h8[idx] = p[0] * w[d] + p[1] * w[DM + d] + p[2] * w[2 * DM + d] + b[d];
}

__global__ void k_assemble(const float* __restrict__ s0, const float* __restrict__ s1,
                           const float* __restrict__ posemb) {
    int idx = blockIdx.x * blockDim.x + threadIdx.x;
    if (idx >= MR * DM) return;
    int d = idx % DM;
    int t = (idx / DM) % SEQ;
    int b = idx / (DM * SEQ);
    float v;
    if (t == 0) v = s0[d];
    else if (t <= 64) v = g_h8[(b * 64 + t - 1) * DM + d];
    else if (t == 65) v = s1[d];
    else {
        int p = t - 66;
        int src = ((p >> 6) >> 3) * 8 + ((p & 63) >> 3);
        v = g_h8[(b * 64 + src) * DM + d] + posemb[(size_t)p * DM + d];
    }
    g_x[idx] = v;
}

// ---------------- layernorm -------------------------------------------------
__global__ void k_ln(const float* __restrict__ lnw, const float* __restrict__ lnb) {
    __shared__ float sh[DM];
    __shared__ float red[256];
    int row = blockIdx.x;
    const float* xr = g_x + (size_t)row * DM;
    float s = 0.f;
    for (int i = threadIdx.x; i < DM; i += 256) { float v = xr[i]; sh[i] = v; s += v; }
    float mean = blockSum256(s, red) * (1.f / DM);
    float vs = 0.f;
    for (int i = threadIdx.x; i < DM; i += 256) { float d = sh[i] - mean; vs += d * d; }
    float var = blockSum256(vs, red) * (1.f / DM);
    float inv = rsqrtf(var + 1e-5f);
    float* o = g_ln + (size_t)row * DM;
    for (int i = threadIdx.x; i < DM; i += 256)
        o[i] = (sh[i] - mean) * inv * lnw[i] + lnb[i];
}

// ---------------- tensor-core GEMM (3xTF32): C[M,N] (+)= A[M,K]*B[N,K]^T ----
#define BMT 128
#define BNT 128
#define BKT 16
#define SPITCH 20

__global__ void __launch_bounds__(256, 2)
k_gemm_tc(const float* __restrict__ A, const float* __restrict__ Bm,
          float* __restrict__ C, int M, int N, int K, int accum) {
    __shared__ float As[2][BMT * SPITCH];
    __shared__ float Bs[2][BNT * SPITCH];

    const int tid = threadIdx.x;
    const int lane = tid & 31;
    const int wid = tid >> 5;
    const int warpM = wid >> 1;        // 0..3
    const int warpN = wid & 1;         // 0..1
    const int row0 = blockIdx.y * BMT;
    const int col0 = blockIdx.x * BNT;

    const int lr = lane >> 2;          // 0..7
    const int lc = lane & 3;           // 0..3

    float acc[2][8][4];
#pragma unroll
    for (int mt = 0; mt < 2; mt++)
#pragma unroll
        for (int nt = 0; nt < 8; nt++)
#pragma unroll
            for (int r = 0; r < 4; r++) acc[mt][nt][r] = 0.f;

    const int ntiles = K / BKT;

    // staging registers
    float4 ra[2], rb[2];
    const int r0c = tid >> 2, c0c = tid & 3;
    const int r1c = (tid + 256) >> 2, c1c = tid & 3;

    // prologue: load tile 0
    {
        int gr0 = row0 + r0c, gr1 = row0 + r1c;
        int gc0 = col0 + r0c, gc1 = col0 + r1c;
        const float4 z = make_float4(0.f, 0.f, 0.f, 0.f);
        ra[0] = (gr0 < M) ? *(const float4*)&A[(size_t)gr0 * K + c0c * 4] : z;
        ra[1] = (gr1 < M) ? *(const float4*)&A[(size_t)gr1 * K + c1c * 4] : z;
        rb[0] = (gc0 < N) ? *(const float4*)&Bm[(size_t)gc0 * K + c0c * 4] : z;
        rb[1] = (gc1 < N) ? *(const float4*)&Bm[(size_t)gc1 * K + c1c * 4] : z;
        *(float4*)&As[0][r0c * SPITCH + c0c * 4] = ra[0];
        *(float4*)&As[0][r1c * SPITCH + c1c * 4] = ra[1];
        *(float4*)&Bs[0][r0c * SPITCH + c0c * 4] = rb[0];
        *(float4*)&Bs[0][r1c * SPITCH + c1c * 4] = rb[1];
    }
    __syncthreads();

    for (int t = 0; t < ntiles; t++) {
        int buf = t & 1;
        // prefetch next tile into registers
        if (t + 1 < ntiles) {
            int kof = (t + 1) * BKT;
            int gr0 = row0 + r0c, gr1 = row0 + r1c;
            int gc0 = col0 + r0c, gc1 = col0 + r1c;
            const float4 z = make_float4(0.f, 0.f, 0.f, 0.f);
            ra[0] = (gr0 < M) ? *(const float4*)&A[(size_t)gr0 * K + kof + c0c * 4] : z;
            ra[1] = (gr1 < M) ? *(const float4*)&A[(size_t)gr1 * K + kof + c1c * 4] : z;
            rb[0] = (gc0 < N) ? *(const float4*)&Bm[(size_t)gc0 * K + kof + c0c * 4] : z;
            rb[1] = (gc1 < N) ? *(const float4*)&Bm[(size_t)gc1 * K + kof + c1c * 4] : z;
        }

        // compute on buf  (3xTF32: ah*bh + al*bh + ah*bl)
#pragma unroll
        for (int ks = 0; ks < BKT; ks += 8) {
            uint32_t ah[2][4], al[2][4];
#pragma unroll
            for (int mt = 0; mt < 2; mt++) {
                int m = warpM * 32 + mt * 16 + lr;
                int k = ks + lc;
                tf32split(As[buf][m * SPITCH + k],        ah[mt][0], al[mt][0]);
                tf32split(As[buf][(m + 8) * SPITCH + k],  ah[mt][1], al[mt][1]);
                tf32split(As[buf][m * SPITCH + k + 4],    ah[mt][2], al[mt][2]);
                tf32split(As[buf][(m + 8) * SPITCH + k + 4], ah[mt][3], al[mt][3]);
            }
#pragma unroll
            for (int nt = 0; nt < 8; nt++) {
                int n = warpN * 64 + nt * 8 + lr;
                int k = ks + lc;
                uint32_t bh[2], bl[2];
                tf32split(Bs[buf][n * SPITCH + k],     bh[0], bl[0]);
                tf32split(Bs[buf][n * SPITCH + k + 4], bh[1], bl[1]);
#pragma unroll
                for (int mt = 0; mt < 2; mt++) {
                    asm volatile(
                        "mma.sync.aligned.m16n8k8.row.col.f32.tf32.tf32.f32 "
                        "{%0,%1,%2,%3}, {%4,%5,%6,%7}, {%8,%9}, {%0,%1,%2,%3};"
                        : "+f"(acc[mt][nt][0]), "+f"(acc[mt][nt][1]),
                          "+f"(acc[mt][nt][2]), "+f"(acc[mt][nt][3])
                        : "r"(al[mt][0]), "r"(al[mt][1]), "r"(al[mt][2]), "r"(al[mt][3]),
                          "r"(bh[0]), "r"(bh[1]));
                    asm volatile(
                        "mma.sync.aligned.m16n8k8.row.col.f32.tf32.tf32.f32 "
                        "{%0,%1,%2,%3}, {%4,%5,%6,%7}, {%8,%9}, {%0,%1,%2,%3};"
                        : "+f"(acc[mt][nt][0]), "+f"(acc[mt][nt][1]),
                          "+f"(acc[mt][nt][2]), "+f"(acc[mt][nt][3])
                        : "r"(ah[mt][0]), "r"(ah[mt][1]), "r"(ah[mt][2]), "r"(ah[mt][3]),
                          "r"(bl[0]), "r"(bl[1]));
                    asm volatile(
                        "mma.sync.aligned.m16n8k8.row.col.f32.tf32.tf32.f32 "
                        "{%0,%1,%2,%3}, {%4,%5,%6,%7}, {%8,%9}, {%0,%1,%2,%3};"
                        : "+f"(acc[mt][nt][0]), "+f"(acc[mt][nt][1]),
                          "+f"(acc[mt][nt][2]), "+f"(acc[mt][nt][3])
                        : "r"(ah[mt][0]), "r"(ah[mt][1]), "r"(ah[mt][2]), "r"(ah[mt][3]),
                          "r"(bh[0]), "r"(bh[1]));
                }
            }
        }

        // store prefetched tile into other buffer
        if (t + 1 < ntiles) {
            int nb = (t + 1) & 1;
            *(float4*)&As[nb][r0c * SPITCH + c0c * 4] = ra[0];
            *(float4*)&As[nb][r1c * SPITCH + c1c * 4] = ra[1];
            *(float4*)&Bs[nb][r0c * SPITCH + c0c * 4] = rb[0];
            *(float4*)&Bs[nb][r1c * SPITCH + c1c * 4] = rb[1];
            __syncthreads();
        }
    }

    // epilogue
#pragma unroll
    for (int mt = 0; mt < 2; mt++) {
        int rbase = row0 + warpM * 32 + mt * 16 + lr;
#pragma unroll
        for (int nt = 0; nt < 8; nt++) {
            int cbase = col0 + warpN * 64 + nt * 8 + lc * 2;
            if (rbase < M) {
                if (cbase < N) {
                    size_t o = (size_t)rbase * N + cbase;
                    C[o] = accum ? (C[o] + acc[mt][nt][0]) : acc[mt][nt][0];
                }
                if (cbase + 1 < N) {
                    size_t o = (size_t)rbase * N + cbase + 1;
                    C[o] = accum ? (C[o] + acc[mt][nt][1]) : acc[mt][nt][1];
                }
            }
            if (rbase + 8 < M) {
                if (cbase < N) {
                    size_t o = (size_t)(rbase + 8) * N + cbase;
                    C[o] = accum ? (C[o] + acc[mt][nt][2]) : acc[mt][nt][2];
                }
                if (cbase + 1 < N) {
                    size_t o = (size_t)(rbase + 8) * N + cbase + 1;
                    C[o] = accum ? (C[o] + acc[mt][nt][3]) : acc[mt][nt][3];
                }
            }
        }
    }
}

// ---------------- dt / dA ---------------------------------------------------
__global__ void k_dt(const float* __restrict__ dtb, const float* __restrict__ Alog) {
    int idx = blockIdx.x * blockDim.x + threadIdx.x;
    if (idx >= MR * NH) return;
    int h = idx % NH;
    int row = idx / NH;
    float v = g_zx[(size_t)row * DIP + (DIP - NH) + h] + dtb[h];
    float sp = (v > 20.f) ? v : log1pf(expf(v));
    float A = -expf(Alog[h]);
    g_dt[idx] = sp;
    g_dA[idx] = expf(sp * A);
}

// ---------------- causal depthwise conv (k=4) + silu ------------------------
__global__ void k_conv(const float* __restrict__ cw, const float* __restrict__ cb) {
    int idx = blockIdx.x * blockDim.x + threadIdx.x;
    if (idx >= MR * CONV_DIM) return;
    int c = idx % CONV_DIM;
    int rt = idx / CONV_DIM;
    int t = rt % SEQ;
    int b = rt / SEQ;
    const float4 w = *(const float4*)(cw + c * 4);
    const float wj[4] = {w.x, w.y, w.z, w.w};
    float acc = cb[c];
#pragma unroll
    for (int j = 0; j < 4; j++) {
        int ts = t - 3 + j;
        if (ts >= 0) acc += g_zx[((size_t)(b * SEQ + ts)) * DIP + DI + c] * wj[j];
    }
    g_xBC[idx] = siluf(acc);
}

// ---------------- selective scan --------------------------------------------
#define CHK 64
__global__ void k_scan(const float* __restrict__ Dp) {
    __shared__ float sx[CHK][32];
    __shared__ float sB[CHK][64];
    __shared__ float sC[CHK][64];
    __shared__ float sdA[CHK];
    __shared__ float sdt[CHK];
    int pblk = blockIdx.x;   // 0..3
    int h = blockIdx.y;      // 0..15
    int b = blockIdx.z;      // 0..1
    int tid = threadIdx.x;
    int pl = tid >> 3, ng = tid & 7, n0 = ng * 8;
    int p = pblk * 32 + pl;
    float s[8];
#pragma unroll
    for (int j = 0; j < 8; j++) s[j] = 0.f;
    float Dh = Dp[h];
    size_t baseRow = (size_t)b * SEQ;
    int xoff = h * HD + pblk * 32;
    for (int t0 = 0; t0 < SEQ; t0 += CHK) {
        int cnt = min(CHK, SEQ - t0);
        for (int i = tid; i < cnt * 32; i += 256) {
            int q = i >> 5, ii = i & 31;
            sx[q][ii] = g_xBC[(baseRow + t0 + q) * CONV_DIM + xoff + ii];
        }
        for (int i = tid; i < cnt * 64; i += 256) {
            int q = i >> 6, ii = i & 63;
            sB[q][ii] = g_xBC[(baseRow + t0 + q) * CONV_DIM + DI + ii];
        }
        for (int i = tid; i < cnt * 64; i += 256) {
            int q = i >> 6, ii = i & 63;
            sC[q][ii] = g_xBC[(baseRow + t0 + q) * CONV_DIM + DI + DSTATE + ii];
        }
        for (int i = tid; i < cnt; i += 256) {
            sdA[i] = g_dA[(baseRow + t0 + i) * NH + h];
            sdt[i] = g_dt[(baseRow + t0 + i) * NH + h];
        }
        __syncthreads();
        for (int q = 0; q < cnt; q++) {
            float dA = sdA[q];
            float xp = sx[q][pl];
            float a = sdt[q] * xp;
            float yp = 0.f;
#pragma unroll
            for (int j = 0; j < 8; j++) {
                s[j] = s[j] * dA + a * sB[q][n0 + j];
                yp += s[j] * sC[q][n0 + j];
            }
            yp += __shfl_xor_sync(0xffffffffu, yp, 1);
            yp += __shfl_xor_sync(0xffffffffu, yp, 2);
            yp += __shfl_xor_sync(0xffffffffu, yp, 4);
            if (ng == 0)
                g_y[(baseRow + t0 + q) * DI + h * HD + p] = yp + Dh * xp;
        }
        __syncthreads();
    }
}

// ---------------- gate (silu(z)) + RMSNorm ----------------------------------
__global__ void k_gaterms(const float* __restrict__ rmsw) {
    __shared__ float sh[DI];
    __shared__ float red[256];
    int row = blockIdx.x;
    const float* zr = g_zx + (size_t)row * DIP;
    float* yr = g_y + (size_t)row * DI;
    float ss = 0.f;
    for (int i = threadIdx.x; i < DI; i += 256) {
        float z = zr[i];
        float g = yr[i] * siluf(z);
        sh[i] = g;
        ss += g * g;
    }
    float tot = blockSum256(ss, red);
    float inv = rsqrtf(tot * (1.f / DI) + 1e-5f);
    for (int i = threadIdx.x; i < DI; i += 256)
        yr[i] = sh[i] * inv * rmsw[i];
}

// ---------------- output head + per-pixel squared error ---------------------
__global__ void k_head(const float* __restrict__ w, const float* __restrict__ bias,
                       const float* __restrict__ im64, float* __restrict__ out,
                       int out_size) {
    __shared__ float red[256];
    int r = blockIdx.x;          // 0..NPIX-1
    int b = r / 4096, p = r % 4096;
    const float* xr = g_x + ((size_t)(b * SEQ) + 66 + p) * DM;
    float a0 = 0.f, a1 = 0.f, a2 = 0.f;
    for (int i = threadIdx.x; i < DM; i += 256) {
        float v = xr[i];
        a0 += v * w[i * 3 + 0];
        a1 += v * w[i * 3 + 1];
        a2 += v * w[i * 3 + 2];
    }
    a0 = blockSum256(a0, red);
    a1 = blockSum256(a1, red);
    a2 = blockSum256(a2, red);
    if (threadIdx.x == 0) {
        float y0 = a0 + bias[0], y1 = a1 + bias[1], y2 = a2 + bias[2];
        const float* im = im64 + (size_t)r * 3;
        float e0 = y0 - im[0], e1 = y1 - im[1], e2 = y2 - im[2];
        g_part[r] = e0 * e0 + e1 * e1 + e2 * e2;
        if (out_size >= YHAT_ELEMS) {
            out[(size_t)r * 3 + 0] = y0;
            out[(size_t)r * 3 + 1] = y1;
            out[(size_t)r * 3 + 2] = y2;
        }
    }
}

__global__ void k_loss(float* __restrict__ out, int out_size) {
    __shared__ float red[256];
    float s = 0.f;
    for (int i = threadIdx.x; i < NPIX; i += 256) s += g_part[i];
    float tot = blockSum256(s, red);
    if (threadIdx.x == 0) {
        float loss = tot * (1.f / (float)YHAT_ELEMS);
        if (out_size <= 1) out[0] = loss;
        else if (out_size > YHAT_ELEMS) out[YHAT_ELEMS] = loss;
    }
}

// ---------------- driver -----------------------------------------------------
extern "C" void kernel_launch(void* const* d_in, const int* in_sizes, int n_in,
                              void* d_out, int out_size) {
    const float* im8        = (const float*)d_in[0];
    const float* im64       = (const float*)d_in[1];
    const float* from_rgb_w = (const float*)d_in[2];
    const float* from_rgb_b = (const float*)d_in[3];
    const float* to_rgb_w   = (const float*)d_in[4];
    const float* to_rgb_b   = (const float*)d_in[5];
    const float* s0         = (const float*)d_in[6];
    const float* s1         = (const float*)d_in[7];
    const float* posemb     = (const float*)d_in[8];
    const float* ln_w       = (const float*)d_in[9];
    const float* ln_b       = (const float*)d_in[10];
    const float* in_proj_w  = (const float*)d_in[11];
    const float* conv_w     = (const float*)d_in[12];
    const float* conv_b     = (const float*)d_in[13];
    const float* dt_bias    = (const float*)d_in[14];
    const float* A_log      = (const float*)d_in[15];
    const float* Dp         = (const float*)d_in[16];
    const float* rms_w      = (const float*)d_in[17];
    const float* out_proj_w = (const float*)d_in[18];
    float* out = (float*)d_out;

    float *p_x, *p_ln, *p_zx, *p_y;
    cudaGetSymbolAddress((void**)&p_x, g_x);
    cudaGetSymbolAddress((void**)&p_ln, g_ln);
    cudaGetSymbolAddress((void**)&p_zx, g_zx);
    cudaGetSymbolAddress((void**)&p_y, g_y);

    k_h8<<<(B_SZ * 64 * DM + 255) / 256, 256>>>(im8, from_rgb_w, from_rgb_b);
    k_assemble<<<(MR * DM + 255) / 256, 256>>>(s0, s1, posemb);

    for (int l = 0; l < NL; l++) {
        k_ln<<<MR, 256>>>(ln_w + l * DM, ln_b + l * DM);

        dim3 g1((DIP + BNT - 1) / BNT, (MR + BMT - 1) / BMT);
        k_gemm_tc<<<g1, 256>>>(p_ln, in_proj_w + (size_t)l * DIP * DM, p_zx,
                               MR, DIP, DM, 0);

        k_dt<<<(MR * NH + 255) / 256, 256>>>(dt_bias + l * NH, A_log + l * NH);
        k_conv<<<(MR * CONV_DIM + 255) / 256, 256>>>(conv_w + l * CONV_DIM * 4,
                                                     conv_b + l * CONV_DIM);

        dim3 gs(4, NH, B_SZ);
        k_scan<<<gs, 256>>>(Dp + l * NH);

        k_gaterms<<<MR, 256>>>(rms_w + l * DI);

        dim3 g2((DM + BNT - 1) / BNT, (MR + BMT - 1) / BMT);
        k_gemm_tc<<<g2, 256>>>(p_y, out_proj_w + (size_t)l * DM * DI, p_x,
                               MR, DM, DI, 1);
    }

    k_head<<<NPIX, 256>>>(to_rgb_w, to_rgb_b, im64, out, out_size);
    k_loss<<<1, 256>>>(out, out_size);
}

// round 4
// speedup vs baseline: 2.2610x; 1.2287x over previous
#include <cuda_runtime.h>
#include <cuda_bf16.h>
#include <math.h>
#include <stdint.h>

#define B_SZ 2
#define SEQ 4162
#define DM 1024
#define DI 2048
#define DSTATE 64
#define HD 128
#define NH 16
#define NL 4
#define CONV_DIM 2176
#define DIP 4240
#define MR (B_SZ*SEQ)          // 8324 rows
#define NPIX (B_SZ*4096)       // 8192
#define YHAT_ELEMS (NPIX*3)    // 24576

// ---------------- scratch (static device allocations; no cudaMalloc) -------
__device__ float g_x[(size_t)MR*DM];        // residual stream
__device__ float g_ln[(size_t)MR*DM];       // layernorm output
__device__ float g_zx[(size_t)MR*DIP];      // in_proj output
__device__ float g_xBC[(size_t)MR*CONV_DIM];// conv+silu output
__device__ float g_y[(size_t)MR*DI];        // scan output / gated / rmsnorm
__device__ float g_dt[MR*NH];
__device__ float g_dA[MR*NH];
__device__ float g_h8[B_SZ*64*DM];
__device__ float g_part[NPIX];

// ---------------- helpers ---------------------------------------------------
__device__ __forceinline__ float siluf(float x) { return x / (1.f + expf(-x)); }

__device__ __forceinline__ float blockSum256(float v, float* red) {
    int tid = threadIdx.x;
    red[tid] = v;
    __syncthreads();
#pragma unroll
    for (int s = 128; s > 0; s >>= 1) {
        if (tid < s) red[tid] += red[tid + s];
        __syncthreads();
    }
    float r = red[0];
    __syncthreads();
    return r;
}

// split float pair (x=k even, y=k odd) into packed bf16x2 hi and lo words
__device__ __forceinline__ void bf16split2(float x, float y, uint32_t& hi, uint32_t& lo) {
    __nv_bfloat162 h = __floats2bfloat162_rn(x, y);
    uint32_t hw = *reinterpret_cast<uint32_t*>(&h);
    float hx = __uint_as_float(hw << 16);
    float hy = __uint_as_float(hw & 0xffff0000u);
    __nv_bfloat162 l = __floats2bfloat162_rn(x - hx, y - hy);
    hi = hw;
    lo = *reinterpret_cast<uint32_t*>(&l);
}

// ---------------- stage 0: embed -------------------------------------------
__global__ void k_h8(const float* __restrict__ im8, const float* __restrict__ w,
                     const float* __restrict__ b) {
    int idx = blockIdx.x * blockDim.x + threadIdx.x;
    if (idx >= B_SZ * 64 * DM) return;
    int d = idx % DM;
    int r = idx / DM;  // b*64 + i
    const float* p = im8 + r * 3;
    g_h8[idx] = p[0] * w[d] + p[1] * w[DM + d] + p[2] * w[2 * DM + d] + b[d];
}

__global__ void k_assemble(const float* __restrict__ s0, const float* __restrict__ s1,
                           const float* __restrict__ posemb) {
    int idx = blockIdx.x * blockDim.x + threadIdx.x;
    if (idx >= MR * DM) return;
    int d = idx % DM;
    int t = (idx / DM) % SEQ;
    int b = idx / (DM * SEQ);
    float v;
    if (t == 0) v = s0[d];
    else if (t <= 64) v = g_h8[(b * 64 + t - 1) * DM + d];
    else if (t == 65) v = s1[d];
    else {
        int p = t - 66;
        int src = ((p >> 6) >> 3) * 8 + ((p & 63) >> 3);
        v = g_h8[(b * 64 + src) * DM + d] + posemb[(size_t)p * DM + d];
    }
    g_x[idx] = v;
}

// ---------------- layernorm -------------------------------------------------
__global__ void k_ln(const float* __restrict__ lnw, const float* __restrict__ lnb) {
    __shared__ float sh[DM];
    __shared__ float red[256];
    int row = blockIdx.x;
    const float* xr = g_x + (size_t)row * DM;
    float s = 0.f;
    for (int i = threadIdx.x; i < DM; i += 256) { float v = xr[i]; sh[i] = v; s += v; }
    float mean = blockSum256(s, red) * (1.f / DM);
    float vs = 0.f;
    for (int i = threadIdx.x; i < DM; i += 256) { float d = sh[i] - mean; vs += d * d; }
    float var = blockSum256(vs, red) * (1.f / DM);
    float inv = rsqrtf(var + 1e-5f);
    float* o = g_ln + (size_t)row * DM;
    for (int i = threadIdx.x; i < DM; i += 256)
        o[i] = (sh[i] - mean) * inv * lnw[i] + lnb[i];
}

// ---------------- tensor-core GEMM (bf16x3): C[M,N] (+)= A[M,K]*B[N,K]^T ----
// mma.m16n8k16 bf16, 128x128 block tile, BK=16, double-buffered smem.
// smem tiles hold hi/lo bf16 pairs, pitch 12 words (24 bf16) -> conflict-free.
#define BMT 128
#define BNT 128
#define BKT 16
#define PW 12   // pitch in 32-bit words per row

__global__ void __launch_bounds__(256, 2)
k_gemm_tc(const float* __restrict__ A, const float* __restrict__ Bm,
          float* __restrict__ C, int M, int N, int K, int accum) {
    __shared__ uint32_t Ah[2][BMT * PW];
    __shared__ uint32_t Al[2][BMT * PW];
    __shared__ uint32_t Bh[2][BNT * PW];
    __shared__ uint32_t Bl[2][BNT * PW];

    const int tid = threadIdx.x;
    const int lane = tid & 31;
    const int wid = tid >> 5;
    const int warpM = wid >> 1;        // 0..3
    const int warpN = wid & 1;         // 0..1
    const int row0 = blockIdx.y * BMT;
    const int col0 = blockIdx.x * BNT;

    const int lr = lane >> 2;          // 0..7
    const int lc = lane & 3;           // 0..3

    float acc[2][8][4];
#pragma unroll
    for (int mt = 0; mt < 2; mt++)
#pragma unroll
        for (int nt = 0; nt < 8; nt++)
#pragma unroll
            for (int r = 0; r < 4; r++) acc[mt][nt][r] = 0.f;

    const int ntiles = K / BKT;

    // staging registers
    float4 ra[2], rb[2];
    const int r0c = tid >> 2, c0c = tid & 3;       // row 0..63, k-quad
    const int r1c = (tid + 256) >> 2;              // row 64..127, same quad

    // prologue: load + split + store tile 0
    {
        int gr0 = row0 + r0c, gr1 = row0 + r1c;
        int gc0 = col0 + r0c, gc1 = col0 + r1c;
        const float4 z = make_float4(0.f, 0.f, 0.f, 0.f);
        ra[0] = (gr0 < M) ? *(const float4*)&A[(size_t)gr0 * K + c0c * 4] : z;
        ra[1] = (gr1 < M) ? *(const float4*)&A[(size_t)gr1 * K + c0c * 4] : z;
        rb[0] = (gc0 < N) ? *(const float4*)&Bm[(size_t)gc0 * K + c0c * 4] : z;
        rb[1] = (gc1 < N) ? *(const float4*)&Bm[(size_t)gc1 * K + c0c * 4] : z;
        uint32_t h0, l0, h1, l1;
#pragma unroll
        for (int u = 0; u < 2; u++) {
            int rrow = (u == 0) ? r0c : r1c;
            int base = rrow * PW + c0c * 2;
            bf16split2(ra[u].x, ra[u].y, h0, l0);
            bf16split2(ra[u].z, ra[u].w, h1, l1);
            Ah[0][base] = h0; Ah[0][base + 1] = h1;
            Al[0][base] = l0; Al[0][base + 1] = l1;
            bf16split2(rb[u].x, rb[u].y, h0, l0);
            bf16split2(rb[u].z, rb[u].w, h1, l1);
            Bh[0][base] = h0; Bh[0][base + 1] = h1;
            Bl[0][base] = l0; Bl[0][base + 1] = l1;
        }
    }
    __syncthreads();

    for (int t = 0; t < ntiles; t++) {
        int buf = t & 1;
        // prefetch next tile into registers
        if (t + 1 < ntiles) {
            int kof = (t + 1) * BKT;
            int gr0 = row0 + r0c, gr1 = row0 + r1c;
            int gc0 = col0 + r0c, gc1 = col0 + r1c;
            const float4 z = make_float4(0.f, 0.f, 0.f, 0.f);
            ra[0] = (gr0 < M) ? *(const float4*)&A[(size_t)gr0 * K + kof + c0c * 4] : z;
            ra[1] = (gr1 < M) ? *(const float4*)&A[(size_t)gr1 * K + kof + c0c * 4] : z;
            rb[0] = (gc0 < N) ? *(const float4*)&Bm[(size_t)gc0 * K + kof + c0c * 4] : z;
            rb[1] = (gc1 < N) ? *(const float4*)&Bm[(size_t)gc1 * K + kof + c0c * 4] : z;
        }

        // fragments (k16 spans the whole BK=16 tile)
        uint32_t ah[2][4], al[2][4];
#pragma unroll
        for (int mt = 0; mt < 2; mt++) {
            int m = warpM * 32 + mt * 16 + lr;
            int idx = m * PW + lc;
            ah[mt][0] = Ah[buf][idx];        al[mt][0] = Al[buf][idx];
            ah[mt][1] = Ah[buf][idx + 8*PW]; al[mt][1] = Al[buf][idx + 8*PW];
            ah[mt][2] = Ah[buf][idx + 4];    al[mt][2] = Al[buf][idx + 4];
            ah[mt][3] = Ah[buf][idx + 8*PW + 4]; al[mt][3] = Al[buf][idx + 8*PW + 4];
        }
#pragma unroll
        for (int nt = 0; nt < 8; nt++) {
            int n = warpN * 64 + nt * 8 + lr;
            int bidx = n * PW + lc;
            uint32_t bh0 = Bh[buf][bidx], bh1 = Bh[buf][bidx + 4];
            uint32_t bl0 = Bl[buf][bidx], bl1 = Bl[buf][bidx + 4];
#pragma unroll
            for (int mt = 0; mt < 2; mt++) {
                asm volatile(
                    "mma.sync.aligned.m16n8k16.row.col.f32.bf16.bf16.f32 "
                    "{%0,%1,%2,%3}, {%4,%5,%6,%7}, {%8,%9}, {%0,%1,%2,%3};"
                    : "+f"(acc[mt][nt][0]), "+f"(acc[mt][nt][1]),
                      "+f"(acc[mt][nt][2]), "+f"(acc[mt][nt][3])
                    : "r"(al[mt][0]), "r"(al[mt][1]), "r"(al[mt][2]), "r"(al[mt][3]),
                      "r"(bh0), "r"(bh1));
                asm volatile(
                    "mma.sync.aligned.m16n8k16.row.col.f32.bf16.bf16.f32 "
                    "{%0,%1,%2,%3}, {%4,%5,%6,%7}, {%8,%9}, {%0,%1,%2,%3};"
                    : "+f"(acc[mt][nt][0]), "+f"(acc[mt][nt][1]),
                      "+f"(acc[mt][nt][2]), "+f"(acc[mt][nt][3])
                    : "r"(ah[mt][0]), "r"(ah[mt][1]), "r"(ah[mt][2]), "r"(ah[mt][3]),
                      "r"(bl0), "r"(bl1));
                asm volatile(
                    "mma.sync.aligned.m16n8k16.row.col.f32.bf16.bf16.f32 "
                    "{%0,%1,%2,%3}, {%4,%5,%6,%7}, {%8,%9}, {%0,%1,%2,%3};"
                    : "+f"(acc[mt][nt][0]), "+f"(acc[mt][nt][1]),
                      "+f"(acc[mt][nt][2]), "+f"(acc[mt][nt][3])
                    : "r"(ah[mt][0]), "r"(ah[mt][1]), "r"(ah[mt][2]), "r"(ah[mt][3]),
                      "r"(bh0), "r"(bh1));
            }
        }

        // split + store prefetched tile into other buffer
        if (t + 1 < ntiles) {
            int nb = (t + 1) & 1;
            __syncthreads();   // all reads of buf done before overwriting? (nb != buf, safe) -- needed before reuse of nb
            uint32_t h0, l0, h1, l1;
#pragma unroll
            for (int u = 0; u < 2; u++) {
                int rrow = (u == 0) ? r0c : r1c;
                int base = rrow * PW + c0c * 2;
                bf16split2(ra[u].x, ra[u].y, h0, l0);
                bf16split2(ra[u].z, ra[u].w, h1, l1);
                Ah[nb][base] = h0; Ah[nb][base + 1] = h1;
                Al[nb][base] = l0; Al[nb][base + 1] = l1;
                bf16split2(rb[u].x, rb[u].y, h0, l0);
                bf16split2(rb[u].z, rb[u].w, h1, l1);
                Bh[nb][base] = h0; Bh[nb][base + 1] = h1;
                Bl[nb][base] = l0; Bl[nb][base + 1] = l1;
            }
            __syncthreads();
        }
    }

    // epilogue
#pragma unroll
    for (int mt = 0; mt < 2; mt++) {
        int rbase = row0 + warpM * 32 + mt * 16 + lr;
#pragma unroll
        for (int nt = 0; nt < 8; nt++) {
            int cbase = col0 + warpN * 64 + nt * 8 + lc * 2;
            if (rbase < M) {
                if (cbase < N) {
                    size_t o = (size_t)rbase * N + cbase;
                    C[o] = accum ? (C[o] + acc[mt][nt][0]) : acc[mt][nt][0];
                }
                if (cbase + 1 < N) {
                    size_t o = (size_t)rbase * N + cbase + 1;
                    C[o] = accum ? (C[o] + acc[mt][nt][1]) : acc[mt][nt][1];
                }
            }
            if (rbase + 8 < M) {
                if (cbase < N) {
                    size_t o = (size_t)(rbase + 8) * N + cbase;
                    C[o] = accum ? (C[o] + acc[mt][nt][2]) : acc[mt][nt][2];
                }
                if (cbase + 1 < N) {
                    size_t o = (size_t)(rbase + 8) * N + cbase + 1;
                    C[o] = accum ? (C[o] + acc[mt][nt][3]) : acc[mt][nt][3];
                }
            }
        }
    }
}

// ---------------- dt / dA ---------------------------------------------------
__global__ void k_dt(const float* __restrict__ dtb, const float* __restrict__ Alog) {
    int idx = blockIdx.x * blockDim.x + threadIdx.x;
    if (idx >= MR * NH) return;
    int h = idx % NH;
    int row = idx / NH;
    float v = g_zx[(size_t)row * DIP + (DIP - NH) + h] + dtb[h];
    float sp = (v > 20.f) ? v : log1pf(expf(v));
    float A = -expf(Alog[h]);
    g_dt[idx] = sp;
    g_dA[idx] = expf(sp * A);
}

// ---------------- causal depthwise conv (k=4) + silu ------------------------
__global__ void k_conv(const float* __restrict__ cw, const float* __restrict__ cb) {
    int idx = blockIdx.x * blockDim.x + threadIdx.x;
    if (idx >= MR * CONV_DIM) return;
    int c = idx % CONV_DIM;
    int rt = idx / CONV_DIM;
    int t = rt % SEQ;
    int b = rt / SEQ;
    const float4 w = *(const float4*)(cw + c * 4);
    const float wj[4] = {w.x, w.y, w.z, w.w};
    float acc = cb[c];
#pragma unroll
    for (int j = 0; j < 4; j++) {
        int ts = t - 3 + j;
        if (ts >= 0) acc += g_zx[((size_t)(b * SEQ + ts)) * DIP + DI + c] * wj[j];
    }
    g_xBC[idx] = siluf(acc);
}

// ---------------- selective scan --------------------------------------------
#define CHK 64
__global__ void k_scan(const float* __restrict__ Dp) {
    __shared__ float sx[CHK][32];
    __shared__ float sB[CHK][64];
    __shared__ float sC[CHK][64];
    __shared__ float sdA[CHK];
    __shared__ float sdt[CHK];
    int pblk = blockIdx.x;   // 0..3
    int h = blockIdx.y;      // 0..15
    int b = blockIdx.z;      // 0..1
    int tid = threadIdx.x;
    int pl = tid >> 3, ng = tid & 7, n0 = ng * 8;
    int p = pblk * 32 + pl;
    float s[8];
#pragma unroll
    for (int j = 0; j < 8; j++) s[j] = 0.f;
    float Dh = Dp[h];
    size_t baseRow = (size_t)b * SEQ;
    int xoff = h * HD + pblk * 32;
    for (int t0 = 0; t0 < SEQ; t0 += CHK) {
        int cnt = min(CHK, SEQ - t0);
        for (int i = tid; i < cnt * 32; i += 256) {
            int q = i >> 5, ii = i & 31;
            sx[q][ii] = g_xBC[(baseRow + t0 + q) * CONV_DIM + xoff + ii];
        }
        for (int i = tid; i < cnt * 64; i += 256) {
            int q = i >> 6, ii = i & 63;
            sB[q][ii] = g_xBC[(baseRow + t0 + q) * CONV_DIM + DI + ii];
        }
        for (int i = tid; i < cnt * 64; i += 256) {
            int q = i >> 6, ii = i & 63;
            sC[q][ii] = g_xBC[(baseRow + t0 + q) * CONV_DIM + DI + DSTATE + ii];
        }
        for (int i = tid; i < cnt; i += 256) {
            sdA[i] = g_dA[(baseRow + t0 + i) * NH + h];
            sdt[i] = g_dt[(baseRow + t0 + i) * NH + h];
        }
        __syncthreads();
        for (int q = 0; q < cnt; q++) {
            float dA = sdA[q];
            float xp = sx[q][pl];
            float a = sdt[q] * xp;
            float yp = 0.f;
#pragma unroll
            for (int j = 0; j < 8; j++) {
                s[j] = s[j] * dA + a * sB[q][n0 + j];
                yp += s[j] * sC[q][n0 + j];
            }
            yp += __shfl_xor_sync(0xffffffffu, yp, 1);
            yp += __shfl_xor_sync(0xffffffffu, yp, 2);
            yp += __shfl_xor_sync(0xffffffffu, yp, 4);
            if (ng == 0)
                g_y[(baseRow + t0 + q) * DI + h * HD + p] = yp + Dh * xp;
        }
        __syncthreads();
    }
}

// ---------------- gate (silu(z)) + RMSNorm ----------------------------------
__global__ void k_gaterms(const float* __restrict__ rmsw) {
    __shared__ float sh[DI];
    __shared__ float red[256];
    int row = blockIdx.x;
    const float* zr = g_zx + (size_t)row * DIP;
    float* yr = g_y + (size_t)row * DI;
    float ss = 0.f;
    for (int i = threadIdx.x; i < DI; i += 256) {
        float z = zr[i];
        float g = yr[i] * siluf(z);
        sh[i] = g;
        ss += g * g;
    }
    float tot = blockSum256(ss, red);
    float inv = rsqrtf(tot * (1.f / DI) + 1e-5f);
    for (int i = threadIdx.x; i < DI; i += 256)
        yr[i] = sh[i] * inv * rmsw[i];
}

// ---------------- output head + per-pixel squared error ---------------------
__global__ void k_head(const float* __restrict__ w, const float* __restrict__ bias,
                       const float* __restrict__ im64, float* __restrict__ out,
                       int out_size) {
    __shared__ float red[256];
    int r = blockIdx.x;          // 0..NPIX-1
    int b = r / 4096, p = r % 4096;
    const float* xr = g_x + ((size_t)(b * SEQ) + 66 + p) * DM;
    float a0 = 0.f, a1 = 0.f, a2 = 0.f;
    for (int i = threadIdx.x; i < DM; i += 256) {
        float v = xr[i];
        a0 += v * w[i * 3 + 0];
        a1 += v * w[i * 3 + 1];
        a2 += v * w[i * 3 + 2];
    }
    a0 = blockSum256(a0, red);
    a1 = blockSum256(a1, red);
    a2 = blockSum256(a2, red);
    if (threadIdx.x == 0) {
        float y0 = a0 + bias[0], y1 = a1 + bias[1], y2 = a2 + bias[2];
        const float* im = im64 + (size_t)r * 3;
        float e0 = y0 - im[0], e1 = y1 - im[1], e2 = y2 - im[2];
        g_part[r] = e0 * e0 + e1 * e1 + e2 * e2;
        if (out_size >= YHAT_ELEMS) {
            out[(size_t)r * 3 + 0] = y0;
            out[(size_t)r * 3 + 1] = y1;
            out[(size_t)r * 3 + 2] = y2;
        }
    }
}

__global__ void k_loss(float* __restrict__ out, int out_size) {
    __shared__ float red[256];
    float s = 0.f;
    for (int i = threadIdx.x; i < NPIX; i += 256) s += g_part[i];
    float tot = blockSum256(s, red);
    if (threadIdx.x == 0) {
        float loss = tot * (1.f / (float)YHAT_ELEMS);
        if (out_size <= 1) out[0] = loss;
        else if (out_size > YHAT_ELEMS) out[YHAT_ELEMS] = loss;
    }
}

// ---------------- driver -----------------------------------------------------
extern "C" void kernel_launch(void* const* d_in, const int* in_sizes, int n_in,
                              void* d_out, int out_size) {
    const float* im8        = (const float*)d_in[0];
    const float* im64       = (const float*)d_in[1];
    const float* from_rgb_w = (const float*)d_in[2];
    const float* from_rgb_b = (const float*)d_in[3];
    const float* to_rgb_w   = (const float*)d_in[4];
    const float* to_rgb_b   = (const float*)d_in[5];
    const float* s0         = (const float*)d_in[6];
    const float* s1         = (const float*)d_in[7];
    const float* posemb     = (const float*)d_in[8];
    const float* ln_w       = (const float*)d_in[9];
    const float* ln_b       = (const float*)d_in[10];
    const float* in_proj_w  = (const float*)d_in[11];
    const float* conv_w     = (const float*)d_in[12];
    const float* conv_b     = (const float*)d_in[13];
    const float* dt_bias    = (const float*)d_in[14];
    const float* A_log      = (const float*)d_in[15];
    const float* Dp         = (const float*)d_in[16];
    const float* rms_w      = (const float*)d_in[17];
    const float* out_proj_w = (const float*)d_in[18];
    float* out = (float*)d_out;

    float *p_x, *p_ln, *p_zx, *p_y;
    cudaGetSymbolAddress((void**)&p_x, g_x);
    cudaGetSymbolAddress((void**)&p_ln, g_ln);
    cudaGetSymbolAddress((void**)&p_zx, g_zx);
    cudaGetSymbolAddress((void**)&p_y, g_y);

    k_h8<<<(B_SZ * 64 * DM + 255) / 256, 256>>>(im8, from_rgb_w, from_rgb_b);
    k_assemble<<<(MR * DM + 255) / 256, 256>>>(s0, s1, posemb);

    for (int l = 0; l < NL; l++) {
        k_ln<<<MR, 256>>>(ln_w + l * DM, ln_b + l * DM);

        dim3 g1((DIP + BNT - 1) / BNT, (MR + BMT - 1) / BMT);
        k_gemm_tc<<<g1, 256>>>(p_ln, in_proj_w + (size_t)l * DIP * DM, p_zx,
                               MR, DIP, DM, 0);

        k_dt<<<(MR * NH + 255) / 256, 256>>>(dt_bias + l * NH, A_log + l * NH);
        k_conv<<<(MR * CONV_DIM + 255) / 256, 256>>>(conv_w + l * CONV_DIM * 4,
                                                     conv_b + l * CONV_DIM);

        dim3 gs(4, NH, B_SZ);
        k_scan<<<gs, 256>>>(Dp + l * NH);

        k_gaterms<<<MR, 256>>>(rms_w + l * DI);

        dim3 g2((DM + BNT - 1) / BNT, (MR + BMT - 1) / BMT);
        k_gemm_tc<<<g2, 256>>>(p_y, out_proj_w + (size_t)l * DM * DI, p_x,
                               MR, DM, DI, 1);
    }

    k_head<<<NPIX, 256>>>(to_rgb_w, to_rgb_b, im64, out, out_size);
    k_loss<<<1, 256>>>(out, out_size);
}

// round 6
// speedup vs baseline: 2.5342x; 1.1208x over previous
#include <cuda_runtime.h>
#include <cuda_bf16.h>
#include <math.h>
#include <stdint.h>

#define B_SZ 2
#define SEQ 4162
#define DM 1024
#define DI 2048
#define DSTATE 64
#define HD 128
#define NH 16
#define NL 4
#define CONV_DIM 2176
#define DIP 4240
#define MR (B_SZ*SEQ)          // 8324 rows
#define NPIX (B_SZ*4096)       // 8192
#define YHAT_ELEMS (NPIX*3)    // 24576

// ---------------- scratch (static device allocations; no cudaMalloc) -------
__device__ float g_x[(size_t)MR*DM];        // residual stream
__device__ float g_ln[(size_t)MR*DM];       // layernorm output
__device__ float g_zx[(size_t)MR*DIP];      // in_proj output
__device__ float g_xBC[(size_t)MR*CONV_DIM];// conv+silu output
__device__ float g_y[(size_t)MR*DI];        // scan output / gated / rmsnorm
__device__ float g_dt[MR*NH];
__device__ float g_dA[MR*NH];
__device__ float g_h8[B_SZ*64*DM];
__device__ float g_part[NPIX];

// ---------------- helpers ---------------------------------------------------
__device__ __forceinline__ float siluf(float x) { return x / (1.f + expf(-x)); }

// warp-shuffle block reduction, 256 threads, 2 barriers
__device__ __forceinline__ float blockSum256(float v, float* red8) {
    int lane = threadIdx.x & 31, wid = threadIdx.x >> 5;
#pragma unroll
    for (int o = 16; o; o >>= 1) v += __shfl_xor_sync(0xffffffffu, v, o);
    if (lane == 0) red8[wid] = v;
    __syncthreads();
    float r = 0.f;
#pragma unroll
    for (int i = 0; i < 8; i++) r += red8[i];
    __syncthreads();
    return r;
}

// split float pair (x=k even, y=k odd) into packed bf16x2 hi and lo words
__device__ __forceinline__ void bf16split2(float x, float y, uint32_t& hi, uint32_t& lo) {
    __nv_bfloat162 h = __floats2bfloat162_rn(x, y);
    uint32_t hw = *reinterpret_cast<uint32_t*>(&h);
    float hx = __uint_as_float(hw << 16);
    float hy = __uint_as_float(hw & 0xffff0000u);
    __nv_bfloat162 l = __floats2bfloat162_rn(x - hx, y - hy);
    hi = hw;
    lo = *reinterpret_cast<uint32_t*>(&l);
}

__device__ __forceinline__ uint32_t smem_u32(const void* p) {
    uint32_t a;
    asm("{ .reg .u64 t; cvta.to.shared.u64 t, %1; cvt.u32.u64 %0, t; }"
        : "=r"(a) : "l"(p));
    return a;
}

__device__ __forceinline__ void ldsm4(uint32_t a, uint32_t& r0, uint32_t& r1,
                                      uint32_t& r2, uint32_t& r3) {
    asm volatile("ldmatrix.sync.aligned.m8n8.x4.shared.b16 {%0,%1,%2,%3}, [%4];"
                 : "=r"(r0), "=r"(r1), "=r"(r2), "=r"(r3) : "r"(a));
}

// ---------------- stage 0: embed -------------------------------------------
__global__ void k_h8(const float* __restrict__ im8, const float* __restrict__ w,
                     const float* __restrict__ b) {
    int idx = blockIdx.x * blockDim.x + threadIdx.x;
    if (idx >= B_SZ * 64 * DM) return;
    int d = idx % DM;
    int r = idx / DM;  // b*64 + i
    const float* p = im8 + r * 3;
    g_h8[idx] = p[0] * w[d] + p[1] * w[DM + d] + p[2] * w[2 * DM + d] + b[d];
}

__global__ void k_assemble(const float* __restrict__ s0, const float* __restrict__ s1,
                           const float* __restrict__ posemb) {
    int idx = blockIdx.x * blockDim.x + threadIdx.x;
    if (idx >= MR * DM) return;
    int d = idx % DM;
    int t = (idx / DM) % SEQ;
    int b = idx / (DM * SEQ);
    float v;
    if (t == 0) v = s0[d];
    else if (t <= 64) v = g_h8[(b * 64 + t - 1) * DM + d];
    else if (t == 65) v = s1[d];
    else {
        int p = t - 66;
        int src = ((p >> 6) >> 3) * 8 + ((p & 63) >> 3);
        v = g_h8[(b * 64 + src) * DM + d] + posemb[(size_t)p * DM + d];
    }
    g_x[idx] = v;
}

// ---------------- layernorm (float4, shuffle reductions) --------------------
__global__ void k_ln(const float* __restrict__ lnw, const float* __restrict__ lnb) {
    __shared__ float red8[8];
    int row = blockIdx.x, tid = threadIdx.x;
    const float4* xr = (const float4*)(g_x + (size_t)row * DM);
    float4 v = xr[tid];
    float mean = blockSum256(v.x + v.y + v.z + v.w, red8) * (1.f / DM);
    float dx = v.x - mean, dy = v.y - mean, dz = v.z - mean, dw = v.w - mean;
    float var = blockSum256(dx * dx + dy * dy + dz * dz + dw * dw, red8) * (1.f / DM);
    float inv = rsqrtf(var + 1e-5f);
    float4 w4 = ((const float4*)lnw)[tid];
    float4 b4 = ((const float4*)lnb)[tid];
    float4 o;
    o.x = dx * inv * w4.x + b4.x;
    o.y = dy * inv * w4.y + b4.y;
    o.z = dz * inv * w4.z + b4.z;
    o.w = dw * inv * w4.w + b4.w;
    ((float4*)(g_ln + (size_t)row * DM))[tid] = o;
}

// ---------------- tensor-core GEMM (bf16x3 + ldmatrix) ----------------------
// C[M,N] (+)= A[M,K] * B[N,K]^T. mma.m16n8k16 bf16, 128x128 tile, BK=16,
// double-buffered smem, hi/lo bf16 tiles at pitch 12 words (conflict-free).
#define BMT 128
#define BNT 128
#define BKT 16
#define PW 12   // pitch in 32-bit words per row
#define TILEB (BMT * PW * 4)   // bytes per tile buffer

__global__ void __launch_bounds__(256, 2)
k_gemm_tc(const float* __restrict__ A, const float* __restrict__ Bm,
          float* __restrict__ C, int M, int N, int K, int accum) {
    __shared__ uint32_t Ah[2][BMT * PW];
    __shared__ uint32_t Al[2][BMT * PW];
    __shared__ uint32_t Bh[2][BNT * PW];
    __shared__ uint32_t Bl[2][BNT * PW];

    const int tid = threadIdx.x;
    const int lane = tid & 31;
    const int wid = tid >> 5;
    const int warpM = wid >> 1;        // 0..3
    const int warpN = wid & 1;         // 0..1
    const int row0 = blockIdx.y * BMT;
    const int col0 = blockIdx.x * BNT;

    const int lr = lane >> 2;          // 0..7
    const int lc = lane & 3;           // 0..3

    // ldmatrix lane addressing
    const int grp = lane >> 3, lrow = lane & 7;
    const int a_mrow = (grp & 1) * 8 + lrow;      // +0/+8 within 16-row tile
    const int a_koff = (grp >> 1) * 16;           // 0 / 16 bytes
    const int b_nrow = (grp >> 1) * 8 + lrow;     // +0/+8 within 16-col pair
    const int b_koff = (grp & 1) * 16;            // 0 / 16 bytes

    const uint32_t sAh = smem_u32(Ah), sAl = smem_u32(Al);
    const uint32_t sBh = smem_u32(Bh), sBl = smem_u32(Bl);

    float acc[2][8][4];
#pragma unroll
    for (int mt = 0; mt < 2; mt++)
#pragma unroll
        for (int nt = 0; nt < 8; nt++)
#pragma unroll
            for (int r = 0; r < 4; r++) acc[mt][nt][r] = 0.f;

    const int ntiles = K / BKT;

    float4 ra[2], rb[2];
    const int r0c = tid >> 2, c0c = tid & 3;       // row 0..63, k-quad
    const int r1c = (tid + 256) >> 2;              // row 64..127

    // prologue: load + split + store tile 0
    {
        int gr0 = row0 + r0c, gr1 = row0 + r1c;
        int gc0 = col0 + r0c, gc1 = col0 + r1c;
        const float4 z = make_float4(0.f, 0.f, 0.f, 0.f);
        ra[0] = (gr0 < M) ? *(const float4*)&A[(size_t)gr0 * K + c0c * 4] : z;
        ra[1] = (gr1 < M) ? *(const float4*)&A[(size_t)gr1 * K + c0c * 4] : z;
        rb[0] = (gc0 < N) ? *(const float4*)&Bm[(size_t)gc0 * K + c0c * 4] : z;
        rb[1] = (gc1 < N) ? *(const float4*)&Bm[(size_t)gc1 * K + c0c * 4] : z;
        uint32_t h0, l0, h1, l1;
#pragma unroll
        for (int u = 0; u < 2; u++) {
            int rrow = (u == 0) ? r0c : r1c;
            int base = rrow * PW + c0c * 2;
            bf16split2(ra[u].x, ra[u].y, h0, l0);
            bf16split2(ra[u].z, ra[u].w, h1, l1);
            Ah[0][base] = h0; Ah[0][base + 1] = h1;
            Al[0][base] = l0; Al[0][base + 1] = l1;
            bf16split2(rb[u].x, rb[u].y, h0, l0);
            bf16split2(rb[u].z, rb[u].w, h1, l1);
            Bh[0][base] = h0; Bh[0][base + 1] = h1;
            Bl[0][base] = l0; Bl[0][base + 1] = l1;
        }
    }
    __syncthreads();

    for (int t = 0; t < ntiles; t++) {
        int buf = t & 1;
        uint32_t bufoff = buf * TILEB;
        // prefetch next tile into registers
        if (t + 1 < ntiles) {
            int kof = (t + 1) * BKT;
            int gr0 = row0 + r0c, gr1 = row0 + r1c;
            int gc0 = col0 + r0c, gc1 = col0 + r1c;
            const float4 z = make_float4(0.f, 0.f, 0.f, 0.f);
            ra[0] = (gr0 < M) ? *(const float4*)&A[(size_t)gr0 * K + kof + c0c * 4] : z;
            ra[1] = (gr1 < M) ? *(const float4*)&A[(size_t)gr1 * K + kof + c0c * 4] : z;
            rb[0] = (gc0 < N) ? *(const float4*)&Bm[(size_t)gc0 * K + kof + c0c * 4] : z;
            rb[1] = (gc1 < N) ? *(const float4*)&Bm[(size_t)gc1 * K + kof + c0c * 4] : z;
        }

        // A fragments via ldmatrix (hi + lo)
        uint32_t ah[2][4], al[2][4];
#pragma unroll
        for (int mt = 0; mt < 2; mt++) {
            uint32_t aoff = bufoff + (warpM * 32 + mt * 16 + a_mrow) * (PW * 4) + a_koff;
            ldsm4(sAh + aoff, ah[mt][0], ah[mt][1], ah[mt][2], ah[mt][3]);
            ldsm4(sAl + aoff, al[mt][0], al[mt][1], al[mt][2], al[mt][3]);
        }

        // B fragments per nt-pair + MMAs
#pragma unroll
        for (int ntp = 0; ntp < 4; ntp++) {
            uint32_t boff = bufoff + (warpN * 64 + ntp * 16 + b_nrow) * (PW * 4) + b_koff;
            uint32_t bh[4], bl[4];
            ldsm4(sBh + boff, bh[0], bh[1], bh[2], bh[3]);
            ldsm4(sBl + boff, bl[0], bl[1], bl[2], bl[3]);
#pragma unroll
            for (int par = 0; par < 2; par++) {
                int nt = ntp * 2 + par;
                uint32_t b0h = bh[par * 2], b1h = bh[par * 2 + 1];
                uint32_t b0l = bl[par * 2], b1l = bl[par * 2 + 1];
#pragma unroll
                for (int mt = 0; mt < 2; mt++) {
                    asm volatile(
                        "mma.sync.aligned.m16n8k16.row.col.f32.bf16.bf16.f32 "
                        "{%0,%1,%2,%3}, {%4,%5,%6,%7}, {%8,%9}, {%0,%1,%2,%3};"
                        : "+f"(acc[mt][nt][0]), "+f"(acc[mt][nt][1]),
                          "+f"(acc[mt][nt][2]), "+f"(acc[mt][nt][3])
                        : "r"(al[mt][0]), "r"(al[mt][1]), "r"(al[mt][2]), "r"(al[mt][3]),
                          "r"(b0h), "r"(b1h));
                    asm volatile(
                        "mma.sync.aligned.m16n8k16.row.col.f32.bf16.bf16.f32 "
                        "{%0,%1,%2,%3}, {%4,%5,%6,%7}, {%8,%9}, {%0,%1,%2,%3};"
                        : "+f"(acc[mt][nt][0]), "+f"(acc[mt][nt][1]),
                          "+f"(acc[mt][nt][2]), "+f"(acc[mt][nt][3])
                        : "r"(ah[mt][0]), "r"(ah[mt][1]), "r"(ah[mt][2]), "r"(ah[mt][3]),
                          "r"(b0l), "r"(b1l));
                    asm volatile(
                        "mma.sync.aligned.m16n8k16.row.col.f32.bf16.bf16.f32 "
                        "{%0,%1,%2,%3}, {%4,%5,%6,%7}, {%8,%9}, {%0,%1,%2,%3};"
                        : "+f"(acc[mt][nt][0]), "+f"(acc[mt][nt][1]),
                          "+f"(acc[mt][nt][2]), "+f"(acc[mt][nt][3])
                        : "r"(ah[mt][0]), "r"(ah[mt][1]), "r"(ah[mt][2]), "r"(ah[mt][3]),
                          "r"(b0h), "r"(b1h));
                }
            }
        }

        // split + store prefetched tile into other buffer
        if (t + 1 < ntiles) {
            int nb = (t + 1) & 1;
            __syncthreads();
            uint32_t h0, l0, h1, l1;
#pragma unroll
            for (int u = 0; u < 2; u++) {
                int rrow = (u == 0) ? r0c : r1c;
                int base = rrow * PW + c0c * 2;
                bf16split2(ra[u].x, ra[u].y, h0, l0);
                bf16split2(ra[u].z, ra[u].w, h1, l1);
                Ah[nb][base] = h0; Ah[nb][base + 1] = h1;
                Al[nb][base] = l0; Al[nb][base + 1] = l1;
                bf16split2(rb[u].x, rb[u].y, h0, l0);
                bf16split2(rb[u].z, rb[u].w, h1, l1);
                Bh[nb][base] = h0; Bh[nb][base + 1] = h1;
                Bl[nb][base] = l0; Bl[nb][base + 1] = l1;
            }
            __syncthreads();
        }
    }

    // epilogue
#pragma unroll
    for (int mt = 0; mt < 2; mt++) {
        int rbase = row0 + warpM * 32 + mt * 16 + lr;
#pragma unroll
        for (int nt = 0; nt < 8; nt++) {
            int cbase = col0 + warpN * 64 + nt * 8 + lc * 2;
            if (rbase < M) {
                if (cbase < N) {
                    size_t o = (size_t)rbase * N + cbase;
                    C[o] = accum ? (C[o] + acc[mt][nt][0]) : acc[mt][nt][0];
                }
                if (cbase + 1 < N) {
                    size_t o = (size_t)rbase * N + cbase + 1;
                    C[o] = accum ? (C[o] + acc[mt][nt][1]) : acc[mt][nt][1];
                }
            }
            if (rbase + 8 < M) {
                if (cbase < N) {
                    size_t o = (size_t)(rbase + 8) * N + cbase;
                    C[o] = accum ? (C[o] + acc[mt][nt][2]) : acc[mt][nt][2];
                }
                if (cbase + 1 < N) {
                    size_t o = (size_t)(rbase + 8) * N + cbase + 1;
                    C[o] = accum ? (C[o] + acc[mt][nt][3]) : acc[mt][nt][3];
                }
            }
        }
    }
}

// ---------------- dt / dA ---------------------------------------------------
__global__ void k_dt(const float* __restrict__ dtb, const float* __restrict__ Alog) {
    int idx = blockIdx.x * blockDim.x + threadIdx.x;
    if (idx >= MR * NH) return;
    int h = idx % NH;
    int row = idx / NH;
    float v = g_zx[(size_t)row * DIP + (DIP - NH) + h] + dtb[h];
    float sp = (v > 20.f) ? v : log1pf(expf(v));
    float A = -expf(Alog[h]);
    g_dt[idx] = sp;
    g_dA[idx] = expf(sp * A);
}

// ---------------- causal depthwise conv (k=4) + silu, float4 ----------------
__global__ void k_conv(const float* __restrict__ cw, const float* __restrict__ cb) {
    int idx = blockIdx.x * blockDim.x + threadIdx.x;
    if (idx >= MR * (CONV_DIM / 4)) return;
    int c4 = idx % (CONV_DIM / 4);
    int rt = idx / (CONV_DIM / 4);
    int t = rt % SEQ;
    int b = rt / SEQ;
    int c = c4 * 4;
    float4 wv[4];
#pragma unroll
    for (int u = 0; u < 4; u++) wv[u] = *(const float4*)(cw + (c + u) * 4);
    float4 bias = *(const float4*)(cb + c);
    float acc0 = bias.x, acc1 = bias.y, acc2 = bias.z, acc3 = bias.w;
    const float wt0[4] = {wv[0].x, wv[0].y, wv[0].z, wv[0].w};
    const float wt1[4] = {wv[1].x, wv[1].y, wv[1].z, wv[1].w};
    const float wt2[4] = {wv[2].x, wv[2].y, wv[2].z, wv[2].w};
    const float wt3[4] = {wv[3].x, wv[3].y, wv[3].z, wv[3].w};
#pragma unroll
    for (int j = 0; j < 4; j++) {
        int ts = t - 3 + j;
        if (ts >= 0) {
            float4 xv = *(const float4*)&g_zx[((size_t)(b * SEQ + ts)) * DIP + DI + c];
            acc0 += xv.x * wt0[j];
            acc1 += xv.y * wt1[j];
            acc2 += xv.z * wt2[j];
            acc3 += xv.w * wt3[j];
        }
    }
    float4 o = make_float4(siluf(acc0), siluf(acc1), siluf(acc2), siluf(acc3));
    *(float4*)&g_xBC[(size_t)rt * CONV_DIM + c] = o;
}

// ---------------- selective scan --------------------------------------------
#define CHK 64
__global__ void k_scan(const float* __restrict__ Dp) {
    __shared__ float sx[CHK][32];
    __shared__ float sB[CHK][64];
    __shared__ float sC[CHK][64];
    __shared__ float sdA[CHK];
    __shared__ float sdt[CHK];
    int pblk = blockIdx.x;   // 0..3
    int h = blockIdx.y;      // 0..15
    int b = blockIdx.z;      // 0..1
    int tid = threadIdx.x;
    int pl = tid >> 3, ng = tid & 7, n0 = ng * 8;
    int p = pblk * 32 + pl;
    float s[8];
#pragma unroll
    for (int j = 0; j < 8; j++) s[j] = 0.f;
    float Dh = Dp[h];
    size_t baseRow = (size_t)b * SEQ;
    int xoff = h * HD + pblk * 32;
    for (int t0 = 0; t0 < SEQ; t0 += CHK) {
        int cnt = min(CHK, SEQ - t0);
        for (int i = tid; i < cnt * 32; i += 256) {
            int q = i >> 5, ii = i & 31;
            sx[q][ii] = g_xBC[(baseRow + t0 + q) * CONV_DIM + xoff + ii];
        }
        for (int i = tid; i < cnt * 64; i += 256) {
            int q = i >> 6, ii = i & 63;
            sB[q][ii] = g_xBC[(baseRow + t0 + q) * CONV_DIM + DI + ii];
        }
        for (int i = tid; i < cnt * 64; i += 256) {
            int q = i >> 6, ii = i & 63;
            sC[q][ii] = g_xBC[(baseRow + t0 + q) * CONV_DIM + DI + DSTATE + ii];
        }
        for (int i = tid; i < cnt; i += 256) {
            sdA[i] = g_dA[(baseRow + t0 + i) * NH + h];
            sdt[i] = g_dt[(baseRow + t0 + i) * NH + h];
        }
        __syncthreads();
        for (int q = 0; q < cnt; q++) {
            float dA = sdA[q];
            float xp = sx[q][pl];
            float a = sdt[q] * xp;
            float yp = 0.f;
#pragma unroll
            for (int j = 0; j < 8; j++) {
                s[j] = s[j] * dA + a * sB[q][n0 + j];
                yp += s[j] * sC[q][n0 + j];
            }
            yp += __shfl_xor_sync(0xffffffffu, yp, 1);
            yp += __shfl_xor_sync(0xffffffffu, yp, 2);
            yp += __shfl_xor_sync(0xffffffffu, yp, 4);
            if (ng == 0)
                g_y[(baseRow + t0 + q) * DI + h * HD + p] = yp + Dh * xp;
        }
        __syncthreads();
    }
}

// ---------------- gate (silu(z)) + RMSNorm (float4, shuffle) -----------------
__global__ void k_gaterms(const float* __restrict__ rmsw) {
    __shared__ float red8[8];
    int row = blockIdx.x, tid = threadIdx.x;
    const float4* zr = (const float4*)(g_zx + (size_t)row * DIP);
    float4* yr = (float4*)(g_y + (size_t)row * DI);
    float4 z0 = zr[tid], z1 = zr[tid + 256];
    float4 y0 = yr[tid], y1 = yr[tid + 256];
    float4 g0, g1;
    g0.x = y0.x * siluf(z0.x); g0.y = y0.y * siluf(z0.y);
    g0.z = y0.z * siluf(z0.z); g0.w = y0.w * siluf(z0.w);
    g1.x = y1.x * siluf(z1.x); g1.y = y1.y * siluf(z1.y);
    g1.z = y1.z * siluf(z1.z); g1.w = y1.w * siluf(z1.w);
    float ss = g0.x * g0.x + g0.y * g0.y + g0.z * g0.z + g0.w * g0.w
             + g1.x * g1.x + g1.y * g1.y + g1.z * g1.z + g1.w * g1.w;
    float tot = blockSum256(ss, red8);
    float inv = rsqrtf(tot * (1.f / DI) + 1e-5f);
    float4 w0 = ((const float4*)rmsw)[tid], w1 = ((const float4*)rmsw)[tid + 256];
    g0.x *= inv * w0.x; g0.y *= inv * w0.y; g0.z *= inv * w0.z; g0.w *= inv * w0.w;
    g1.x *= inv * w1.x; g1.y *= inv * w1.y; g1.z *= inv * w1.z; g1.w *= inv * w1.w;
    yr[tid] = g0;
    yr[tid + 256] = g1;
}

// ---------------- output head: warp per pixel --------------------------------
__global__ void k_head(const float* __restrict__ w, const float* __restrict__ bias,
                       const float* __restrict__ im64, float* __restrict__ out,
                       int out_size) {
    __shared__ float sw[DM * 3];
    int tid = threadIdx.x;
    for (int i = tid; i < DM * 3; i += 256) sw[i] = w[i];
    __syncthreads();
    int lane = tid & 31, wid = tid >> 5;
    int r = blockIdx.x * 8 + wid;      // 0..NPIX-1
    int b = r / 4096, p = r % 4096;
    const float* xr = g_x + ((size_t)(b * SEQ) + 66 + p) * DM;
    float a0 = 0.f, a1 = 0.f, a2 = 0.f;
    for (int i = lane; i < DM; i += 32) {
        float v = xr[i];
        a0 += v * sw[i * 3 + 0];
        a1 += v * sw[i * 3 + 1];
        a2 += v * sw[i * 3 + 2];
    }
#pragma unroll
    for (int o = 16; o; o >>= 1) {
        a0 += __shfl_xor_sync(0xffffffffu, a0, o);
        a1 += __shfl_xor_sync(0xffffffffu, a1, o);
        a2 += __shfl_xor_sync(0xffffffffu, a2, o);
    }
    if (lane == 0) {
        float y0 = a0 + bias[0], y1 = a1 + bias[1], y2 = a2 + bias[2];
        const float* im = im64 + (size_t)r * 3;
        float e0 = y0 - im[0], e1 = y1 - im[1], e2 = y2 - im[2];
        g_part[r] = e0 * e0 + e1 * e1 + e2 * e2;
        if (out_size >= YHAT_ELEMS) {
            out[(size_t)r * 3 + 0] = y0;
            out[(size_t)r * 3 + 1] = y1;
            out[(size_t)r * 3 + 2] = y2;
        }
    }
}

__global__ void k_loss(float* __restrict__ out, int out_size) {
    __shared__ float red8[8];
    float s = 0.f;
    for (int i = threadIdx.x; i < NPIX; i += 256) s += g_part[i];
    float tot = blockSum256(s, red8);
    if (threadIdx.x == 0) {
        float loss = tot * (1.f / (float)YHAT_ELEMS);
        if (out_size <= 1) out[0] = loss;
        else if (out_size > YHAT_ELEMS) out[YHAT_ELEMS] = loss;
    }
}

// ---------------- driver -----------------------------------------------------
extern "C" void kernel_launch(void* const* d_in, const int* in_sizes, int n_in,
                              void* d_out, int out_size) {
    const float* im8        = (const float*)d_in[0];
    const float* im64       = (const float*)d_in[1];
    const float* from_rgb_w = (const float*)d_in[2];
    const float* from_rgb_b = (const float*)d_in[3];
    const float* to_rgb_w   = (const float*)d_in[4];
    const float* to_rgb_b   = (const float*)d_in[5];
    const float* s0         = (const float*)d_in[6];
    const float* s1         = (const float*)d_in[7];
    const float* posemb     = (const float*)d_in[8];
    const float* ln_w       = (const float*)d_in[9];
    const float* ln_b       = (const float*)d_in[10];
    const float* in_proj_w  = (const float*)d_in[11];
    const float* conv_w     = (const float*)d_in[12];
    const float* conv_b     = (const float*)d_in[13];
    const float* dt_bias    = (const float*)d_in[14];
    const float* A_log      = (const float*)d_in[15];
    const float* Dp         = (const float*)d_in[16];
    const float* rms_w      = (const float*)d_in[17];
    const float* out_proj_w = (const float*)d_in[18];
    float* out = (float*)d_out;

    float *p_x, *p_ln, *p_zx, *p_y;
    cudaGetSymbolAddress((void**)&p_x, g_x);
    cudaGetSymbolAddress((void**)&p_ln, g_ln);
    cudaGetSymbolAddress((void**)&p_zx, g_zx);
    cudaGetSymbolAddress((void**)&p_y, g_y);

    k_h8<<<(B_SZ * 64 * DM + 255) / 256, 256>>>(im8, from_rgb_w, from_rgb_b);
    k_assemble<<<(MR * DM + 255) / 256, 256>>>(s0, s1, posemb);

    for (int l = 0; l < NL; l++) {
        k_ln<<<MR, 256>>>(ln_w + l * DM, ln_b + l * DM);

        dim3 g1((DIP + BNT - 1) / BNT, (MR + BMT - 1) / BMT);
        k_gemm_tc<<<g1, 256>>>(p_ln, in_proj_w + (size_t)l * DIP * DM, p_zx,
                               MR, DIP, DM, 0);

        k_dt<<<(MR * NH + 255) / 256, 256>>>(dt_bias + l * NH, A_log + l * NH);
        k_conv<<<(MR * (CONV_DIM / 4) + 255) / 256, 256>>>(conv_w + l * CONV_DIM * 4,
                                                           conv_b + l * CONV_DIM);

        dim3 gs(4, NH, B_SZ);
        k_scan<<<gs, 256>>>(Dp + l * NH);

        k_gaterms<<<MR, 256>>>(rms_w + l * DI);

        dim3 g2((DM + BNT - 1) / BNT, (MR + BMT - 1) / BMT);
        k_gemm_tc<<<g2, 256>>>(p_y, out_proj_w + (size_t)l * DM * DI, p_x,
                               MR, DM, DI, 1);
    }

    k_head<<<NPIX / 8, 256>>>(to_rgb_w, to_rgb_b, im64, out, out_size);
    k_loss<<<1, 256>>>(out, out_size);
}

// round 7
// speedup vs baseline: 2.7994x; 1.1047x over previous
#include <cuda_runtime.h>
#include <cuda_bf16.h>
#include <math.h>
#include <stdint.h>

#define B_SZ 2
#define SEQ 4162
#define DM 1024
#define DI 2048
#define DSTATE 64
#define HD 128
#define NH 16
#define NL 4
#define CONV_DIM 2176
#define DIP 4240
#define MR (B_SZ*SEQ)          // 8324 rows
#define NPIX (B_SZ*4096)       // 8192
#define YHAT_ELEMS (NPIX*3)    // 24576

// ---------------- scratch (static device allocations; no cudaMalloc) -------
__device__ float g_x[(size_t)MR*DM];        // residual stream
__device__ float g_zx[(size_t)MR*DIP];      // in_proj output
__device__ float g_xBC[(size_t)MR*CONV_DIM];// conv+silu output
__device__ float g_y[(size_t)MR*DI];        // scan output
__device__ float g_dt[MR*NH];
__device__ float g_dA[MR*NH];
__device__ float g_h8[B_SZ*64*DM];
__device__ float g_part[NPIX];
// bf16 hi/lo split buffers
__device__ __nv_bfloat16 g_lnh[(size_t)MR*DM];
__device__ __nv_bfloat16 g_lnl[(size_t)MR*DM];
__device__ __nv_bfloat16 g_yh[(size_t)MR*DI];
__device__ __nv_bfloat16 g_yl[(size_t)MR*DI];
__device__ __nv_bfloat16 g_w1h[(size_t)NL*DIP*DM];
__device__ __nv_bfloat16 g_w1l[(size_t)NL*DIP*DM];
__device__ __nv_bfloat16 g_w2h[(size_t)NL*DM*DI];
__device__ __nv_bfloat16 g_w2l[(size_t)NL*DM*DI];

// ---------------- helpers ---------------------------------------------------
__device__ __forceinline__ float siluf(float x) { return x / (1.f + expf(-x)); }

__device__ __forceinline__ float blockSum256(float v, float* red8) {
    int lane = threadIdx.x & 31, wid = threadIdx.x >> 5;
#pragma unroll
    for (int o = 16; o; o >>= 1) v += __shfl_xor_sync(0xffffffffu, v, o);
    if (lane == 0) red8[wid] = v;
    __syncthreads();
    float r = 0.f;
#pragma unroll
    for (int i = 0; i < 8; i++) r += red8[i];
    __syncthreads();
    return r;
}

__device__ __forceinline__ void bf16split2(float x, float y, uint32_t& hi, uint32_t& lo) {
    __nv_bfloat162 h = __floats2bfloat162_rn(x, y);
    uint32_t hw = *reinterpret_cast<uint32_t*>(&h);
    float hx = __uint_as_float(hw << 16);
    float hy = __uint_as_float(hw & 0xffff0000u);
    __nv_bfloat162 l = __floats2bfloat162_rn(x - hx, y - hy);
    hi = hw;
    lo = *reinterpret_cast<uint32_t*>(&l);
}

__device__ __forceinline__ uint32_t smem_u32(const void* p) {
    uint32_t a;
    asm("{ .reg .u64 t; cvta.to.shared.u64 t, %1; cvt.u32.u64 %0, t; }"
        : "=r"(a) : "l"(p));
    return a;
}

__device__ __forceinline__ void ldsm4(uint32_t a, uint32_t& r0, uint32_t& r1,
                                      uint32_t& r2, uint32_t& r3) {
    asm volatile("ldmatrix.sync.aligned.m8n8.x4.shared.b16 {%0,%1,%2,%3}, [%4];"
                 : "=r"(r0), "=r"(r1), "=r"(r2), "=r"(r3) : "r"(a));
}

__device__ __forceinline__ void cp16(uint32_t dst, const void* src, bool v) {
    int sz = v ? 16 : 0;
    asm volatile("cp.async.ca.shared.global [%0], [%1], 16, %2;"
                 :: "r"(dst), "l"(src), "r"(sz));
}

// ---------------- weight split ----------------------------------------------
__global__ void k_wsplit(const float* __restrict__ w, __nv_bfloat16* __restrict__ h,
                         __nv_bfloat16* __restrict__ l, int n) {
    int i = blockIdx.x * blockDim.x + threadIdx.x;
    if (i >= n / 2) return;
    float2 v = ((const float2*)w)[i];
    uint32_t hi, lo;
    bf16split2(v.x, v.y, hi, lo);
    ((uint32_t*)h)[i] = hi;
    ((uint32_t*)l)[i] = lo;
}

// ---------------- stage 0: embed -------------------------------------------
__global__ void k_h8(const float* __restrict__ im8, const float* __restrict__ w,
                     const float* __restrict__ b) {
    int idx = blockIdx.x * blockDim.x + threadIdx.x;
    if (idx >= B_SZ * 64 * DM) return;
    int d = idx % DM;
    int r = idx / DM;
    const float* p = im8 + r * 3;
    g_h8[idx] = p[0] * w[d] + p[1] * w[DM + d] + p[2] * w[2 * DM + d] + b[d];
}

__global__ void k_assemble(const float* __restrict__ s0, const float* __restrict__ s1,
                           const float* __restrict__ posemb) {
    int idx = blockIdx.x * blockDim.x + threadIdx.x;
    if (idx >= MR * DM) return;
    int d = idx % DM;
    int t = (idx / DM) % SEQ;
    int b = idx / (DM * SEQ);
    float v;
    if (t == 0) v = s0[d];
    else if (t <= 64) v = g_h8[(b * 64 + t - 1) * DM + d];
    else if (t == 65) v = s1[d];
    else {
        int p = t - 66;
        int src = ((p >> 6) >> 3) * 8 + ((p & 63) >> 3);
        v = g_h8[(b * 64 + src) * DM + d] + posemb[(size_t)p * DM + d];
    }
    g_x[idx] = v;
}

// ---------------- layernorm -> bf16 hi/lo ------------------------------------
__global__ void k_ln(const float* __restrict__ lnw, const float* __restrict__ lnb) {
    __shared__ float red8[8];
    int row = blockIdx.x, tid = threadIdx.x;
    const float4* xr = (const float4*)(g_x + (size_t)row * DM);
    float4 v = xr[tid];
    float mean = blockSum256(v.x + v.y + v.z + v.w, red8) * (1.f / DM);
    float dx = v.x - mean, dy = v.y - mean, dz = v.z - mean, dw = v.w - mean;
    float var = blockSum256(dx * dx + dy * dy + dz * dz + dw * dw, red8) * (1.f / DM);
    float inv = rsqrtf(var + 1e-5f);
    float4 w4 = ((const float4*)lnw)[tid];
    float4 b4 = ((const float4*)lnb)[tid];
    float ox = dx * inv * w4.x + b4.x;
    float oy = dy * inv * w4.y + b4.y;
    float oz = dz * inv * w4.z + b4.z;
    float ow = dw * inv * w4.w + b4.w;
    uint32_t h0, l0, h1, l1;
    bf16split2(ox, oy, h0, l0);
    bf16split2(oz, ow, h1, l1);
    size_t o = (size_t)row * (DM / 4) + tid;
    ((uint2*)g_lnh)[o] = make_uint2(h0, h1);
    ((uint2*)g_lnl)[o] = make_uint2(l0, l1);
}

// ---------------- tensor-core GEMM (pre-split bf16x3 + cp.async) -------------
// C[M,N] (+)= A[M,K] * B[N,K]^T, A/B given as bf16 hi+lo arrays (K-major).
// 128x128 tile, BK=32 bf16, 2-stage cp.async pipeline, ldmatrix fragments.
#define BMT 128
#define BNT 128
#define BK2 32
#define RPITCH 80            // bytes per smem row (64 data + 16 pad)
#define ARRB (BMT * RPITCH)  // 10240 bytes per tile array
#define STAGEB (4 * ARRB)    // 40960 per stage
#define GSMEM (2 * STAGEB)   // 81920 total

__global__ void __launch_bounds__(256, 2)
k_gemm_bs(const __nv_bfloat16* __restrict__ Ah, const __nv_bfloat16* __restrict__ Al,
          const __nv_bfloat16* __restrict__ Bh, const __nv_bfloat16* __restrict__ Bl,
          float* __restrict__ C, int M, int N, int K, int accum) {
    extern __shared__ char smem[];
    const uint32_t sb = smem_u32(smem);
    const int tid = threadIdx.x;
    const int lane = tid & 31;
    const int wid = tid >> 5;
    const int warpM = wid >> 1;
    const int warpN = wid & 1;
    const int row0 = blockIdx.y * BMT;
    const int col0 = blockIdx.x * BNT;

    const int lr = lane >> 2, lc = lane & 3;
    const int grp = lane >> 3, lrow = lane & 7;
    const int a_mrow = (grp & 1) * 8 + lrow;
    const int a_koff = (grp >> 1) * 16;
    const int b_nrow = (grp >> 1) * 8 + lrow;
    const int b_koff = (grp & 1) * 16;

    float acc[2][8][4];
#pragma unroll
    for (int mt = 0; mt < 2; mt++)
#pragma unroll
        for (int nt = 0; nt < 8; nt++)
#pragma unroll
            for (int r = 0; r < 4; r++) acc[mt][nt][r] = 0.f;

    const int ntiles = K / BK2;

    // per-thread load chunks: 512 x 16B per array per stage, 2 per thread
    const int ch0 = tid, ch1 = tid + 256;
    const int r0 = ch0 >> 2, c0 = ch0 & 3;
    const int r1 = ch1 >> 2, c1 = ch1 & 3;

    auto issue_stage = [&](int t, int buf) {
        int k0 = t * BK2;
        uint32_t s0 = sb + buf * STAGEB;
#pragma unroll
        for (int u = 0; u < 2; u++) {
            int r = u ? r1 : r0;
            int c = u ? c1 : c0;
            uint32_t doff = r * RPITCH + c * 16;
            int gra = row0 + r;
            bool va = gra < M;
            int grac = va ? gra : 0;
            size_t aoff = (size_t)grac * K + k0 + c * 8;
            cp16(s0 + doff, Ah + aoff, va);
            cp16(s0 + ARRB + doff, Al + aoff, va);
            int grb = col0 + r;
            bool vb = grb < N;
            int grbc = vb ? grb : 0;
            size_t boff = (size_t)grbc * K + k0 + c * 8;
            cp16(s0 + 2 * ARRB + doff, Bh + boff, vb);
            cp16(s0 + 3 * ARRB + doff, Bl + boff, vb);
        }
        asm volatile("cp.async.commit_group;");
    };

    issue_stage(0, 0);
    if (ntiles > 1) issue_stage(1, 1);
    else asm volatile("cp.async.commit_group;");

    for (int t = 0; t < ntiles; t++) {
        int buf = t & 1;
        if (t + 2 < ntiles) asm volatile("cp.async.wait_group 1;");
        else asm volatile("cp.async.wait_group 0;");
        __syncthreads();

        uint32_t sstage = sb + buf * STAGEB;
#pragma unroll
        for (int ks = 0; ks < 2; ks++) {
            uint32_t ah[2][4], al[2][4];
#pragma unroll
            for (int mt = 0; mt < 2; mt++) {
                uint32_t aoff = sstage + (warpM * 32 + mt * 16 + a_mrow) * RPITCH
                                + a_koff + ks * 32;
                ldsm4(aoff, ah[mt][0], ah[mt][1], ah[mt][2], ah[mt][3]);
                ldsm4(aoff + ARRB, al[mt][0], al[mt][1], al[mt][2], al[mt][3]);
            }
#pragma unroll
            for (int ntp = 0; ntp < 4; ntp++) {
                uint32_t boff = sstage + 2 * ARRB
                                + (warpN * 64 + ntp * 16 + b_nrow) * RPITCH
                                + b_koff + ks * 32;
                uint32_t bh[4], bl[4];
                ldsm4(boff, bh[0], bh[1], bh[2], bh[3]);
                ldsm4(boff + ARRB, bl[0], bl[1], bl[2], bl[3]);
#pragma unroll
                for (int par = 0; par < 2; par++) {
                    int nt = ntp * 2 + par;
                    uint32_t b0h = bh[par * 2], b1h = bh[par * 2 + 1];
                    uint32_t b0l = bl[par * 2], b1l = bl[par * 2 + 1];
#pragma unroll
                    for (int mt = 0; mt < 2; mt++) {
                        asm volatile(
                            "mma.sync.aligned.m16n8k16.row.col.f32.bf16.bf16.f32 "
                            "{%0,%1,%2,%3}, {%4,%5,%6,%7}, {%8,%9}, {%0,%1,%2,%3};"
                            : "+f"(acc[mt][nt][0]), "+f"(acc[mt][nt][1]),
                              "+f"(acc[mt][nt][2]), "+f"(acc[mt][nt][3])
                            : "r"(al[mt][0]), "r"(al[mt][1]), "r"(al[mt][2]), "r"(al[mt][3]),
                              "r"(b0h), "r"(b1h));
                        asm volatile(
                            "mma.sync.aligned.m16n8k16.row.col.f32.bf16.bf16.f32 "
                            "{%0,%1,%2,%3}, {%4,%5,%6,%7}, {%8,%9}, {%0,%1,%2,%3};"
                            : "+f"(acc[mt][nt][0]), "+f"(acc[mt][nt][1]),
                              "+f"(acc[mt][nt][2]), "+f"(acc[mt][nt][3])
                            : "r"(ah[mt][0]), "r"(ah[mt][1]), "r"(ah[mt][2]), "r"(ah[mt][3]),
                              "r"(b0l), "r"(b1l));
                        asm volatile(
                            "mma.sync.aligned.m16n8k16.row.col.f32.bf16.bf16.f32 "
                            "{%0,%1,%2,%3}, {%4,%5,%6,%7}, {%8,%9}, {%0,%1,%2,%3};"
                            : "+f"(acc[mt][nt][0]), "+f"(acc[mt][nt][1]),
                              "+f"(acc[mt][nt][2]), "+f"(acc[mt][nt][3])
                            : "r"(ah[mt][0]), "r"(ah[mt][1]), "r"(ah[mt][2]), "r"(ah[mt][3]),
                              "r"(b0h), "r"(b1h));
                    }
                }
            }
        }
        __syncthreads();
        if (t + 2 < ntiles) issue_stage(t + 2, buf);
    }

    // epilogue
#pragma unroll
    for (int mt = 0; mt < 2; mt++) {
        int rbase = row0 + warpM * 32 + mt * 16 + lr;
#pragma unroll
        for (int nt = 0; nt < 8; nt++) {
            int cbase = col0 + warpN * 64 + nt * 8 + lc * 2;
            if (rbase < M) {
                if (cbase < N) {
                    size_t o = (size_t)rbase * N + cbase;
                    C[o] = accum ? (C[o] + acc[mt][nt][0]) : acc[mt][nt][0];
                }
                if (cbase + 1 < N) {
                    size_t o = (size_t)rbase * N + cbase + 1;
                    C[o] = accum ? (C[o] + acc[mt][nt][1]) : acc[mt][nt][1];
                }
            }
            if (rbase + 8 < M) {
                if (cbase < N) {
                    size_t o = (size_t)(rbase + 8) * N + cbase;
                    C[o] = accum ? (C[o] + acc[mt][nt][2]) : acc[mt][nt][2];
                }
                if (cbase + 1 < N) {
                    size_t o = (size_t)(rbase + 8) * N + cbase + 1;
                    C[o] = accum ? (C[o] + acc[mt][nt][3]) : acc[mt][nt][3];
                }
            }
        }
    }
}

// ---------------- dt / dA ---------------------------------------------------
__global__ void k_dt(const float* __restrict__ dtb, const float* __restrict__ Alog) {
    int idx = blockIdx.x * blockDim.x + threadIdx.x;
    if (idx >= MR * NH) return;
    int h = idx % NH;
    int row = idx / NH;
    float v = g_zx[(size_t)row * DIP + (DIP - NH) + h] + dtb[h];
    float sp = (v > 20.f) ? v : log1pf(expf(v));
    float A = -expf(Alog[h]);
    g_dt[idx] = sp;
    g_dA[idx] = expf(sp * A);
}

// ---------------- causal depthwise conv (k=4) + silu, float4 ----------------
__global__ void k_conv(const float* __restrict__ cw, const float* __restrict__ cb) {
    int idx = blockIdx.x * blockDim.x + threadIdx.x;
    if (idx >= MR * (CONV_DIM / 4)) return;
    int c4 = idx % (CONV_DIM / 4);
    int rt = idx / (CONV_DIM / 4);
    int t = rt % SEQ;
    int b = rt / SEQ;
    int c = c4 * 4;
    float4 wv[4];
#pragma unroll
    for (int u = 0; u < 4; u++) wv[u] = *(const float4*)(cw + (c + u) * 4);
    float4 bias = *(const float4*)(cb + c);
    float acc0 = bias.x, acc1 = bias.y, acc2 = bias.z, acc3 = bias.w;
    const float wt0[4] = {wv[0].x, wv[0].y, wv[0].z, wv[0].w};
    const float wt1[4] = {wv[1].x, wv[1].y, wv[1].z, wv[1].w};
    const float wt2[4] = {wv[2].x, wv[2].y, wv[2].z, wv[2].w};
    const float wt3[4] = {wv[3].x, wv[3].y, wv[3].z, wv[3].w};
#pragma unroll
    for (int j = 0; j < 4; j++) {
        int ts = t - 3 + j;
        if (ts >= 0) {
            float4 xv = *(const float4*)&g_zx[((size_t)(b * SEQ + ts)) * DIP + DI + c];
            acc0 += xv.x * wt0[j];
            acc1 += xv.y * wt1[j];
            acc2 += xv.z * wt2[j];
            acc3 += xv.w * wt3[j];
        }
    }
    float4 o = make_float4(siluf(acc0), siluf(acc1), siluf(acc2), siluf(acc3));
    *(float4*)&g_xBC[(size_t)rt * CONV_DIM + c] = o;
}

// ---------------- selective scan (float4 smem reads) -------------------------
#define CHK 64
__global__ void k_scan(const float* __restrict__ Dp) {
    __shared__ float sx[CHK][32];
    __shared__ float sB[CHK][64];
    __shared__ float sC[CHK][64];
    __shared__ float sdA[CHK];
    __shared__ float sdt[CHK];
    int pblk = blockIdx.x;
    int h = blockIdx.y;
    int b = blockIdx.z;
    int tid = threadIdx.x;
    int pl = tid >> 3, ng = tid & 7, n0 = ng * 8;
    int p = pblk * 32 + pl;
    float s[8];
#pragma unroll
    for (int j = 0; j < 8; j++) s[j] = 0.f;
    float Dh = Dp[h];
    size_t baseRow = (size_t)b * SEQ;
    int xoff = h * HD + pblk * 32;
    for (int t0 = 0; t0 < SEQ; t0 += CHK) {
        int cnt = min(CHK, SEQ - t0);
        for (int i = tid; i < cnt * 8; i += 256) {
            int q = i >> 3, ii = i & 7;
            ((float4*)sx[q])[ii] =
                *(const float4*)&g_xBC[(baseRow + t0 + q) * CONV_DIM + xoff + ii * 4];
        }
        for (int i = tid; i < cnt * 16; i += 256) {
            int q = i >> 4, ii = i & 15;
            ((float4*)sB[q])[ii] =
                *(const float4*)&g_xBC[(baseRow + t0 + q) * CONV_DIM + DI + ii * 4];
        }
        for (int i = tid; i < cnt * 16; i += 256) {
            int q = i >> 4, ii = i & 15;
            ((float4*)sC[q])[ii] =
                *(const float4*)&g_xBC[(baseRow + t0 + q) * CONV_DIM + DI + DSTATE + ii * 4];
        }
        for (int i = tid; i < cnt; i += 256) {
            sdA[i] = g_dA[(baseRow + t0 + i) * NH + h];
            sdt[i] = g_dt[(baseRow + t0 + i) * NH + h];
        }
        __syncthreads();
        for (int q = 0; q < cnt; q++) {
            float dA = sdA[q];
            float xp = sx[q][pl];
            float a = sdt[q] * xp;
            float4 bb0 = *(const float4*)&sB[q][n0];
            float4 bb1 = *(const float4*)&sB[q][n0 + 4];
            float4 cc0 = *(const float4*)&sC[q][n0];
            float4 cc1 = *(const float4*)&sC[q][n0 + 4];
            float yp;
            s[0] = s[0] * dA + a * bb0.x; yp  = s[0] * cc0.x;
            s[1] = s[1] * dA + a * bb0.y; yp += s[1] * cc0.y;
            s[2] = s[2] * dA + a * bb0.z; yp += s[2] * cc0.z;
            s[3] = s[3] * dA + a * bb0.w; yp += s[3] * cc0.w;
            s[4] = s[4] * dA + a * bb1.x; yp += s[4] * cc1.x;
            s[5] = s[5] * dA + a * bb1.y; yp += s[5] * cc1.y;
            s[6] = s[6] * dA + a * bb1.z; yp += s[6] * cc1.z;
            s[7] = s[7] * dA + a * bb1.w; yp += s[7] * cc1.w;
            yp += __shfl_xor_sync(0xffffffffu, yp, 1);
            yp += __shfl_xor_sync(0xffffffffu, yp, 2);
            yp += __shfl_xor_sync(0xffffffffu, yp, 4);
            if (ng == 0)
                g_y[(baseRow + t0 + q) * DI + h * HD + p] = yp + Dh * xp;
        }
        __syncthreads();
    }
}

// ---------------- gate + RMSNorm -> bf16 hi/lo --------------------------------
__global__ void k_gaterms(const float* __restrict__ rmsw) {
    __shared__ float red8[8];
    int row = blockIdx.x, tid = threadIdx.x;
    const float4* zr = (const float4*)(g_zx + (size_t)row * DIP);
    const float4* yr = (const float4*)(g_y + (size_t)row * DI);
    float4 z0 = zr[tid], z1 = zr[tid + 256];
    float4 y0 = yr[tid], y1 = yr[tid + 256];
    float4 g0, g1;
    g0.x = y0.x * siluf(z0.x); g0.y = y0.y * siluf(z0.y);
    g0.z = y0.z * siluf(z0.z); g0.w = y0.w * siluf(z0.w);
    g1.x = y1.x * siluf(z1.x); g1.y = y1.y * siluf(z1.y);
    g1.z = y1.z * siluf(z1.z); g1.w = y1.w * siluf(z1.w);
    float ss = g0.x * g0.x + g0.y * g0.y + g0.z * g0.z + g0.w * g0.w
             + g1.x * g1.x + g1.y * g1.y + g1.z * g1.z + g1.w * g1.w;
    float tot = blockSum256(ss, red8);
    float inv = rsqrtf(tot * (1.f / DI) + 1e-5f);
    float4 w0 = ((const float4*)rmsw)[tid], w1 = ((const float4*)rmsw)[tid + 256];
    g0.x *= inv * w0.x; g0.y *= inv * w0.y; g0.z *= inv * w0.z; g0.w *= inv * w0.w;
    g1.x *= inv * w1.x; g1.y *= inv * w1.y; g1.z *= inv * w1.z; g1.w *= inv * w1.w;
    uint32_t h0, l0, h1, l1;
    size_t o = (size_t)row * (DI / 4) + tid;
    bf16split2(g0.x, g0.y, h0, l0);
    bf16split2(g0.z, g0.w, h1, l1);
    ((uint2*)g_yh)[o] = make_uint2(h0, h1);
    ((uint2*)g_yl)[o] = make_uint2(l0, l1);
    bf16split2(g1.x, g1.y, h0, l0);
    bf16split2(g1.z, g1.w, h1, l1);
    ((uint2*)g_yh)[o + 256] = make_uint2(h0, h1);
    ((uint2*)g_yl)[o + 256] = make_uint2(l0, l1);
}

// ---------------- output head: warp per pixel --------------------------------
__global__ void k_head(const float* __restrict__ w, const float* __restrict__ bias,
                       const float* __restrict__ im64, float* __restrict__ out,
                       int out_size) {
    __shared__ float sw[DM * 3];
    int tid = threadIdx.x;
    for (int i = tid; i < DM * 3; i += 256) sw[i] = w[i];
    __syncthreads();
    int lane = tid & 31, wid = tid >> 5;
    int r = blockIdx.x * 8 + wid;
    int b = r / 4096, p = r % 4096;
    const float* xr = g_x + ((size_t)(b * SEQ) + 66 + p) * DM;
    float a0 = 0.f, a1 = 0.f, a2 = 0.f;
    for (int i = lane; i < DM; i += 32) {
        float v = xr[i];
        a0 += v * sw[i * 3 + 0];
        a1 += v * sw[i * 3 + 1];
        a2 += v * sw[i * 3 + 2];
    }
#pragma unroll
    for (int o = 16; o; o >>= 1) {
        a0 += __shfl_xor_sync(0xffffffffu, a0, o);
        a1 += __shfl_xor_sync(0xffffffffu, a1, o);
        a2 += __shfl_xor_sync(0xffffffffu, a2, o);
    }
    if (lane == 0) {
        float y0 = a0 + bias[0], y1 = a1 + bias[1], y2 = a2 + bias[2];
        const float* im = im64 + (size_t)r * 3;
        float e0 = y0 - im[0], e1 = y1 - im[1], e2 = y2 - im[2];
        g_part[r] = e0 * e0 + e1 * e1 + e2 * e2;
        if (out_size >= YHAT_ELEMS) {
            out[(size_t)r * 3 + 0] = y0;
            out[(size_t)r * 3 + 1] = y1;
            out[(size_t)r * 3 + 2] = y2;
        }
    }
}

__global__ void k_loss(float* __restrict__ out, int out_size) {
    __shared__ float red8[8];
    float s = 0.f;
    for (int i = threadIdx.x; i < NPIX; i += 256) s += g_part[i];
    float tot = blockSum256(s, red8);
    if (threadIdx.x == 0) {
        float loss = tot * (1.f / (float)YHAT_ELEMS);
        if (out_size <= 1) out[0] = loss;
        else if (out_size > YHAT_ELEMS) out[YHAT_ELEMS] = loss;
    }
}

// ---------------- driver -----------------------------------------------------
extern "C" void kernel_launch(void* const* d_in, const int* in_sizes, int n_in,
                              void* d_out, int out_size) {
    const float* im8        = (const float*)d_in[0];
    const float* im64       = (const float*)d_in[1];
    const float* from_rgb_w = (const float*)d_in[2];
    const float* from_rgb_b = (const float*)d_in[3];
    const float* to_rgb_w   = (const float*)d_in[4];
    const float* to_rgb_b   = (const float*)d_in[5];
    const float* s0         = (const float*)d_in[6];
    const float* s1         = (const float*)d_in[7];
    const float* posemb     = (const float*)d_in[8];
    const float* ln_w       = (const float*)d_in[9];
    const float* ln_b       = (const float*)d_in[10];
    const float* in_proj_w  = (const float*)d_in[11];
    const float* conv_w     = (const float*)d_in[12];
    const float* conv_b     = (const float*)d_in[13];
    const float* dt_bias    = (const float*)d_in[14];
    const float* A_log      = (const float*)d_in[15];
    const float* Dp         = (const float*)d_in[16];
    const float* rms_w      = (const float*)d_in[17];
    const float* out_proj_w = (const float*)d_in[18];
    float* out = (float*)d_out;

    float *p_x, *p_zx;
    cudaGetSymbolAddress((void**)&p_x, g_x);
    cudaGetSymbolAddress((void**)&p_zx, g_zx);
    __nv_bfloat16 *p_lnh, *p_lnl, *p_yh, *p_yl, *p_w1h, *p_w1l, *p_w2h, *p_w2l;
    cudaGetSymbolAddress((void**)&p_lnh, g_lnh);
    cudaGetSymbolAddress((void**)&p_lnl, g_lnl);
    cudaGetSymbolAddress((void**)&p_yh, g_yh);
    cudaGetSymbolAddress((void**)&p_yl, g_yl);
    cudaGetSymbolAddress((void**)&p_w1h, g_w1h);
    cudaGetSymbolAddress((void**)&p_w1l, g_w1l);
    cudaGetSymbolAddress((void**)&p_w2h, g_w2h);
    cudaGetSymbolAddress((void**)&p_w2l, g_w2l);

    cudaFuncSetAttribute(k_gemm_bs, cudaFuncAttributeMaxDynamicSharedMemorySize,
                         GSMEM);

    // split all weights once
    {
        int n1 = NL * DIP * DM;
        k_wsplit<<<(n1 / 2 + 255) / 256, 256>>>(in_proj_w, p_w1h, p_w1l, n1);
        int n2 = NL * DM * DI;
        k_wsplit<<<(n2 / 2 + 255) / 256, 256>>>(out_proj_w, p_w2h, p_w2l, n2);
    }

    k_h8<<<(B_SZ * 64 * DM + 255) / 256, 256>>>(im8, from_rgb_w, from_rgb_b);
    k_assemble<<<(MR * DM + 255) / 256, 256>>>(s0, s1, posemb);

    for (int l = 0; l < NL; l++) {
        k_ln<<<MR, 256>>>(ln_w + l * DM, ln_b + l * DM);

        dim3 g1((DIP + BNT - 1) / BNT, (MR + BMT - 1) / BMT);
        k_gemm_bs<<<g1, 256, GSMEM>>>(p_lnh, p_lnl,
                                      p_w1h + (size_t)l * DIP * DM,
                                      p_w1l + (size_t)l * DIP * DM,
                                      p_zx, MR, DIP, DM, 0);

        k_dt<<<(MR * NH + 255) / 256, 256>>>(dt_bias + l * NH, A_log + l * NH);
        k_conv<<<(MR * (CONV_DIM / 4) + 255) / 256, 256>>>(conv_w + l * CONV_DIM * 4,
                                                           conv_b + l * CONV_DIM);

        dim3 gs(4, NH, B_SZ);
        k_scan<<<gs, 256>>>(Dp + l * NH);

        k_gaterms<<<MR, 256>>>(rms_w + l * DI);

        dim3 g2((DM + BNT - 1) / BNT, (MR + BMT - 1) / BMT);
        k_gemm_bs<<<g2, 256, GSMEM>>>(p_yh, p_yl,
                                      p_w2h + (size_t)l * DM * DI,
                                      p_w2l + (size_t)l * DM * DI,
                                      p_x, MR, DM, DI, 1);
    }

    k_head<<<NPIX / 8, 256>>>(to_rgb_w, to_rgb_b, im64, out, out_size);
    k_loss<<<1, 256>>>(out, out_size);
}

// round 8
// speedup vs baseline: 3.1952x; 1.1414x over previous
#include <cuda_runtime.h>
#include <cuda_bf16.h>
#include <math.h>
#include <stdint.h>

#define B_SZ 2
#define SEQ 4162
#define DM 1024
#define DI 2048
#define DSTATE 64
#define HD 128
#define NH 16
#define NL 4
#define CONV_DIM 2176
#define DIP 4240
#define MR (B_SZ*SEQ)          // 8324 rows
#define NPIX (B_SZ*4096)       // 8192
#define YHAT_ELEMS (NPIX*3)    // 24576
#define LCH 256                // scan chunk length
#define TCH 17                 // ceil(SEQ/LCH)

// ---------------- scratch (static device allocations; no cudaMalloc) -------
__device__ float g_x[(size_t)MR*DM];        // residual stream
__device__ float g_zx[(size_t)MR*DIP];      // in_proj output
__device__ float g_xBC[(size_t)MR*CONV_DIM];// conv+silu output
__device__ float g_y[(size_t)MR*DI];        // scan output
__device__ float g_dt[MR*NH];
__device__ float g_dA[MR*NH];
__device__ float g_h8[B_SZ*64*DM];
__device__ float g_part[NPIX];
// chunked-scan state buffers
__device__ float g_S[(size_t)B_SZ*NH*TCH*HD*DSTATE];
__device__ float g_Hb[(size_t)B_SZ*NH*TCH*HD*DSTATE];
__device__ float g_P[B_SZ*NH*TCH];
// bf16 hi/lo split buffers
__device__ __nv_bfloat16 g_lnh[(size_t)MR*DM];
__device__ __nv_bfloat16 g_lnl[(size_t)MR*DM];
__device__ __nv_bfloat16 g_yh[(size_t)MR*DI];
__device__ __nv_bfloat16 g_yl[(size_t)MR*DI];
__device__ __nv_bfloat16 g_w1h[(size_t)NL*DIP*DM];
__device__ __nv_bfloat16 g_w1l[(size_t)NL*DIP*DM];
__device__ __nv_bfloat16 g_w2h[(size_t)NL*DM*DI];
__device__ __nv_bfloat16 g_w2l[(size_t)NL*DM*DI];

// ---------------- helpers ---------------------------------------------------
__device__ __forceinline__ float siluf(float x) { return x / (1.f + expf(-x)); }

__device__ __forceinline__ float blockSum256(float v, float* red8) {
    int lane = threadIdx.x & 31, wid = threadIdx.x >> 5;
#pragma unroll
    for (int o = 16; o; o >>= 1) v += __shfl_xor_sync(0xffffffffu, v, o);
    if (lane == 0) red8[wid] = v;
    __syncthreads();
    float r = 0.f;
#pragma unroll
    for (int i = 0; i < 8; i++) r += red8[i];
    __syncthreads();
    return r;
}

__device__ __forceinline__ void bf16split2(float x, float y, uint32_t& hi, uint32_t& lo) {
    __nv_bfloat162 h = __floats2bfloat162_rn(x, y);
    uint32_t hw = *reinterpret_cast<uint32_t*>(&h);
    float hx = __uint_as_float(hw << 16);
    float hy = __uint_as_float(hw & 0xffff0000u);
    __nv_bfloat162 l = __floats2bfloat162_rn(x - hx, y - hy);
    hi = hw;
    lo = *reinterpret_cast<uint32_t*>(&l);
}

__device__ __forceinline__ uint32_t smem_u32(const void* p) {
    uint32_t a;
    asm("{ .reg .u64 t; cvta.to.shared.u64 t, %1; cvt.u32.u64 %0, t; }"
        : "=r"(a) : "l"(p));
    return a;
}

__device__ __forceinline__ void ldsm4(uint32_t a, uint32_t& r0, uint32_t& r1,
                                      uint32_t& r2, uint32_t& r3) {
    asm volatile("ldmatrix.sync.aligned.m8n8.x4.shared.b16 {%0,%1,%2,%3}, [%4];"
                 : "=r"(r0), "=r"(r1), "=r"(r2), "=r"(r3) : "r"(a));
}

__device__ __forceinline__ void cp16(uint32_t dst, const void* src, bool v) {
    int sz = v ? 16 : 0;
    asm volatile("cp.async.ca.shared.global [%0], [%1], 16, %2;"
                 :: "r"(dst), "l"(src), "r"(sz));
}

// ---------------- weight split ----------------------------------------------
__global__ void k_wsplit(const float* __restrict__ w, __nv_bfloat16* __restrict__ h,
                         __nv_bfloat16* __restrict__ l, int n) {
    int i = blockIdx.x * blockDim.x + threadIdx.x;
    if (i >= n / 2) return;
    float2 v = ((const float2*)w)[i];
    uint32_t hi, lo;
    bf16split2(v.x, v.y, hi, lo);
    ((uint32_t*)h)[i] = hi;
    ((uint32_t*)l)[i] = lo;
}

// ---------------- stage 0: embed -------------------------------------------
__global__ void k_h8(const float* __restrict__ im8, const float* __restrict__ w,
                     const float* __restrict__ b) {
    int idx = blockIdx.x * blockDim.x + threadIdx.x;
    if (idx >= B_SZ * 64 * DM) return;
    int d = idx % DM;
    int r = idx / DM;
    const float* p = im8 + r * 3;
    g_h8[idx] = p[0] * w[d] + p[1] * w[DM + d] + p[2] * w[2 * DM + d] + b[d];
}

__global__ void k_assemble(const float* __restrict__ s0, const float* __restrict__ s1,
                           const float* __restrict__ posemb) {
    int idx = blockIdx.x * blockDim.x + threadIdx.x;
    if (idx >= MR * DM) return;
    int d = idx % DM;
    int t = (idx / DM) % SEQ;
    int b = idx / (DM * SEQ);
    float v;
    if (t == 0) v = s0[d];
    else if (t <= 64) v = g_h8[(b * 64 + t - 1) * DM + d];
    else if (t == 65) v = s1[d];
    else {
        int p = t - 66;
        int src = ((p >> 6) >> 3) * 8 + ((p & 63) >> 3);
        v = g_h8[(b * 64 + src) * DM + d] + posemb[(size_t)p * DM + d];
    }
    g_x[idx] = v;
}

// ---------------- layernorm -> bf16 hi/lo ------------------------------------
__global__ void k_ln(const float* __restrict__ lnw, const float* __restrict__ lnb) {
    __shared__ float red8[8];
    int row = blockIdx.x, tid = threadIdx.x;
    const float4* xr = (const float4*)(g_x + (size_t)row * DM);
    float4 v = xr[tid];
    float mean = blockSum256(v.x + v.y + v.z + v.w, red8) * (1.f / DM);
    float dx = v.x - mean, dy = v.y - mean, dz = v.z - mean, dw = v.w - mean;
    float var = blockSum256(dx * dx + dy * dy + dz * dz + dw * dw, red8) * (1.f / DM);
    float inv = rsqrtf(var + 1e-5f);
    float4 w4 = ((const float4*)lnw)[tid];
    float4 b4 = ((const float4*)lnb)[tid];
    float ox = dx * inv * w4.x + b4.x;
    float oy = dy * inv * w4.y + b4.y;
    float oz = dz * inv * w4.z + b4.z;
    float ow = dw * inv * w4.w + b4.w;
    uint32_t h0, l0, h1, l1;
    bf16split2(ox, oy, h0, l0);
    bf16split2(oz, ow, h1, l1);
    size_t o = (size_t)row * (DM / 4) + tid;
    ((uint2*)g_lnh)[o] = make_uint2(h0, h1);
    ((uint2*)g_lnl)[o] = make_uint2(l0, l1);
}

// ---------------- tensor-core GEMM (pre-split bf16x3 + cp.async) -------------
#define BMT 128
#define BNT 128
#define BK2 32
#define RPITCH 80
#define ARRB (BMT * RPITCH)
#define STAGEB (4 * ARRB)
#define GSMEM (2 * STAGEB)

__global__ void __launch_bounds__(256, 2)
k_gemm_bs(const __nv_bfloat16* __restrict__ Ah, const __nv_bfloat16* __restrict__ Al,
          const __nv_bfloat16* __restrict__ Bh, const __nv_bfloat16* __restrict__ Bl,
          float* __restrict__ C, int M, int N, int K, int accum) {
    extern __shared__ char smem[];
    const uint32_t sb = smem_u32(smem);
    const int tid = threadIdx.x;
    const int lane = tid & 31;
    const int wid = tid >> 5;
    const int warpM = wid >> 1;
    const int warpN = wid & 1;
    const int row0 = blockIdx.y * BMT;
    const int col0 = blockIdx.x * BNT;

    const int lr = lane >> 2, lc = lane & 3;
    const int grp = lane >> 3, lrow = lane & 7;
    const int a_mrow = (grp & 1) * 8 + lrow;
    const int a_koff = (grp >> 1) * 16;
    const int b_nrow = (grp >> 1) * 8 + lrow;
    const int b_koff = (grp & 1) * 16;

    float acc[2][8][4];
#pragma unroll
    for (int mt = 0; mt < 2; mt++)
#pragma unroll
        for (int nt = 0; nt < 8; nt++)
#pragma unroll
            for (int r = 0; r < 4; r++) acc[mt][nt][r] = 0.f;

    const int ntiles = K / BK2;
    const int ch0 = tid, ch1 = tid + 256;
    const int r0 = ch0 >> 2, c0 = ch0 & 3;
    const int r1 = ch1 >> 2, c1 = ch1 & 3;

    auto issue_stage = [&](int t, int buf) {
        int k0 = t * BK2;
        uint32_t s0 = sb + buf * STAGEB;
#pragma unroll
        for (int u = 0; u < 2; u++) {
            int r = u ? r1 : r0;
            int c = u ? c1 : c0;
            uint32_t doff = r * RPITCH + c * 16;
            int gra = row0 + r;
            bool va = gra < M;
            int grac = va ? gra : 0;
            size_t aoff = (size_t)grac * K + k0 + c * 8;
            cp16(s0 + doff, Ah + aoff, va);
            cp16(s0 + ARRB + doff, Al + aoff, va);
            int grb = col0 + r;
            bool vb = grb < N;
            int grbc = vb ? grb : 0;
            size_t boff = (size_t)grbc * K + k0 + c * 8;
            cp16(s0 + 2 * ARRB + doff, Bh + boff, vb);
            cp16(s0 + 3 * ARRB + doff, Bl + boff, vb);
        }
        asm volatile("cp.async.commit_group;");
    };

    issue_stage(0, 0);
    if (ntiles > 1) issue_stage(1, 1);
    else asm volatile("cp.async.commit_group;");

    for (int t = 0; t < ntiles; t++) {
        int buf = t & 1;
        if (t + 2 < ntiles) asm volatile("cp.async.wait_group 1;");
        else asm volatile("cp.async.wait_group 0;");
        __syncthreads();

        uint32_t sstage = sb + buf * STAGEB;
#pragma unroll
        for (int ks = 0; ks < 2; ks++) {
            uint32_t ah[2][4], al[2][4];
#pragma unroll
            for (int mt = 0; mt < 2; mt++) {
                uint32_t aoff = sstage + (warpM * 32 + mt * 16 + a_mrow) * RPITCH
                                + a_koff + ks * 32;
                ldsm4(aoff, ah[mt][0], ah[mt][1], ah[mt][2], ah[mt][3]);
                ldsm4(aoff + ARRB, al[mt][0], al[mt][1], al[mt][2], al[mt][3]);
            }
#pragma unroll
            for (int ntp = 0; ntp < 4; ntp++) {
                uint32_t boff = sstage + 2 * ARRB
                                + (warpN * 64 + ntp * 16 + b_nrow) * RPITCH
                                + b_koff + ks * 32;
                uint32_t bh[4], bl[4];
                ldsm4(boff, bh[0], bh[1], bh[2], bh[3]);
                ldsm4(boff + ARRB, bl[0], bl[1], bl[2], bl[3]);
#pragma unroll
                for (int par = 0; par < 2; par++) {
                    int nt = ntp * 2 + par;
                    uint32_t b0h = bh[par * 2], b1h = bh[par * 2 + 1];
                    uint32_t b0l = bl[par * 2], b1l = bl[par * 2 + 1];
#pragma unroll
                    for (int mt = 0; mt < 2; mt++) {
                        asm volatile(
                            "mma.sync.aligned.m16n8k16.row.col.f32.bf16.bf16.f32 "
                            "{%0,%1,%2,%3}, {%4,%5,%6,%7}, {%8,%9}, {%0,%1,%2,%3};"
                            : "+f"(acc[mt][nt][0]), "+f"(acc[mt][nt][1]),
                              "+f"(acc[mt][nt][2]), "+f"(acc[mt][nt][3])
                            : "r"(al[mt][0]), "r"(al[mt][1]), "r"(al[mt][2]), "r"(al[mt][3]),
                              "r"(b0h), "r"(b1h));
                        asm volatile(
                            "mma.sync.aligned.m16n8k16.row.col.f32.bf16.bf16.f32 "
                            "{%0,%1,%2,%3}, {%4,%5,%6,%7}, {%8,%9}, {%0,%1,%2,%3};"
                            : "+f"(acc[mt][nt][0]), "+f"(acc[mt][nt][1]),
                              "+f"(acc[mt][nt][2]), "+f"(acc[mt][nt][3])
                            : "r"(ah[mt][0]), "r"(ah[mt][1]), "r"(ah[mt][2]), "r"(ah[mt][3]),
                              "r"(b0l), "r"(b1l));
                        asm volatile(
                            "mma.sync.aligned.m16n8k16.row.col.f32.bf16.bf16.f32 "
                            "{%0,%1,%2,%3}, {%4,%5,%6,%7}, {%8,%9}, {%0,%1,%2,%3};"
                            : "+f"(acc[mt][nt][0]), "+f"(acc[mt][nt][1]),
                              "+f"(acc[mt][nt][2]), "+f"(acc[mt][nt][3])
                            : "r"(ah[mt][0]), "r"(ah[mt][1]), "r"(ah[mt][2]), "r"(ah[mt][3]),
                              "r"(b0h), "r"(b1h));
                    }
                }
            }
        }
        __syncthreads();
        if (t + 2 < ntiles) issue_stage(t + 2, buf);
    }

#pragma unroll
    for (int mt = 0; mt < 2; mt++) {
        int rbase = row0 + warpM * 32 + mt * 16 + lr;
#pragma unroll
        for (int nt = 0; nt < 8; nt++) {
            int cbase = col0 + warpN * 64 + nt * 8 + lc * 2;
            if (rbase < M) {
                if (cbase < N) {
                    size_t o = (size_t)rbase * N + cbase;
                    C[o] = accum ? (C[o] + acc[mt][nt][0]) : acc[mt][nt][0];
                }
                if (cbase + 1 < N) {
                    size_t o = (size_t)rbase * N + cbase + 1;
                    C[o] = accum ? (C[o] + acc[mt][nt][1]) : acc[mt][nt][1];
                }
            }
            if (rbase + 8 < M) {
                if (cbase < N) {
                    size_t o = (size_t)(rbase + 8) * N + cbase;
                    C[o] = accum ? (C[o] + acc[mt][nt][2]) : acc[mt][nt][2];
                }
                if (cbase + 1 < N) {
                    size_t o = (size_t)(rbase + 8) * N + cbase + 1;
                    C[o] = accum ? (C[o] + acc[mt][nt][3]) : acc[mt][nt][3];
                }
            }
        }
    }
}

// ---------------- dt / dA ---------------------------------------------------
__global__ void k_dt(const float* __restrict__ dtb, const float* __restrict__ Alog) {
    int idx = blockIdx.x * blockDim.x + threadIdx.x;
    if (idx >= MR * NH) return;
    int h = idx % NH;
    int row = idx / NH;
    float v = g_zx[(size_t)row * DIP + (DIP - NH) + h] + dtb[h];
    float sp = (v > 20.f) ? v : log1pf(expf(v));
    float A = -expf(Alog[h]);
    g_dt[idx] = sp;
    g_dA[idx] = expf(sp * A);
}

// ---------------- causal depthwise conv (k=4) + silu, float4 ----------------
__global__ void k_conv(const float* __restrict__ cw, const float* __restrict__ cb) {
    int idx = blockIdx.x * blockDim.x + threadIdx.x;
    if (idx >= MR * (CONV_DIM / 4)) return;
    int c4 = idx % (CONV_DIM / 4);
    int rt = idx / (CONV_DIM / 4);
    int t = rt % SEQ;
    int b = rt / SEQ;
    int c = c4 * 4;
    float4 wv[4];
#pragma unroll
    for (int u = 0; u < 4; u++) wv[u] = *(const float4*)(cw + (c + u) * 4);
    float4 bias = *(const float4*)(cb + c);
    float acc0 = bias.x, acc1 = bias.y, acc2 = bias.z, acc3 = bias.w;
    const float wt0[4] = {wv[0].x, wv[0].y, wv[0].z, wv[0].w};
    const float wt1[4] = {wv[1].x, wv[1].y, wv[1].z, wv[1].w};
    const float wt2[4] = {wv[2].x, wv[2].y, wv[2].z, wv[2].w};
    const float wt3[4] = {wv[3].x, wv[3].y, wv[3].z, wv[3].w};
#pragma unroll
    for (int j = 0; j < 4; j++) {
        int ts = t - 3 + j;
        if (ts >= 0) {
            float4 xv = *(const float4*)&g_zx[((size_t)(b * SEQ + ts)) * DIP + DI + c];
            acc0 += xv.x * wt0[j];
            acc1 += xv.y * wt1[j];
            acc2 += xv.z * wt2[j];
            acc3 += xv.w * wt3[j];
        }
    }
    float4 o = make_float4(siluf(acc0), siluf(acc1), siluf(acc2), siluf(acc3));
    *(float4*)&g_xBC[(size_t)rt * CONV_DIM + c] = o;
}

// ---------------- chunked scan: phase A (local scans) ------------------------
__global__ void k_scanA(const float* __restrict__ Dp) {
    __shared__ float sx[64][32];
    __shared__ float sB[64][64];
    __shared__ float sC[64][64];
    __shared__ float sdA[64];
    __shared__ float sdt[64];
    int c = blockIdx.x >> 2, pblk = blockIdx.x & 3;
    int h = blockIdx.y, b = blockIdx.z;
    int tid = threadIdx.x;
    int pl = tid >> 3, ng = tid & 7, n0 = ng * 8;
    int p = pblk * 32 + pl;
    float s[8];
#pragma unroll
    for (int j = 0; j < 8; j++) s[j] = 0.f;
    float approd = 1.f;
    float Dh = Dp[h];
    size_t baseRow = (size_t)b * SEQ;
    int xoff = h * HD + pblk * 32;
    int t0base = c * LCH;
    int tlim = min(SEQ, t0base + LCH);
    for (int t0 = t0base; t0 < tlim; t0 += 64) {
        int cnt = min(64, tlim - t0);
        for (int i = tid; i < cnt * 8; i += 256) {
            int q = i >> 3, ii = i & 7;
            ((float4*)sx[q])[ii] =
                *(const float4*)&g_xBC[(baseRow + t0 + q) * CONV_DIM + xoff + ii * 4];
        }
        for (int i = tid; i < cnt * 16; i += 256) {
            int q = i >> 4, ii = i & 15;
            ((float4*)sB[q])[ii] =
                *(const float4*)&g_xBC[(baseRow + t0 + q) * CONV_DIM + DI + ii * 4];
        }
        for (int i = tid; i < cnt * 16; i += 256) {
            int q = i >> 4, ii = i & 15;
            ((float4*)sC[q])[ii] =
                *(const float4*)&g_xBC[(baseRow + t0 + q) * CONV_DIM + DI + DSTATE + ii * 4];
        }
        for (int i = tid; i < cnt; i += 256) {
            sdA[i] = g_dA[(baseRow + t0 + i) * NH + h];
            sdt[i] = g_dt[(baseRow + t0 + i) * NH + h];
        }
        __syncthreads();
        for (int q = 0; q < cnt; q++) {
            float dA = sdA[q];
            approd *= dA;
            float xp = sx[q][pl];
            float a = sdt[q] * xp;
            float4 bb0 = *(const float4*)&sB[q][n0];
            float4 bb1 = *(const float4*)&sB[q][n0 + 4];
            float4 cc0 = *(const float4*)&sC[q][n0];
            float4 cc1 = *(const float4*)&sC[q][n0 + 4];
            float yp;
            s[0] = s[0] * dA + a * bb0.x; yp  = s[0] * cc0.x;
            s[1] = s[1] * dA + a * bb0.y; yp += s[1] * cc0.y;
            s[2] = s[2] * dA + a * bb0.z; yp += s[2] * cc0.z;
            s[3] = s[3] * dA + a * bb0.w; yp += s[3] * cc0.w;
            s[4] = s[4] * dA + a * bb1.x; yp += s[4] * cc1.x;
            s[5] = s[5] * dA + a * bb1.y; yp += s[5] * cc1.y;
            s[6] = s[6] * dA + a * bb1.z; yp += s[6] * cc1.z;
            s[7] = s[7] * dA + a * bb1.w; yp += s[7] * cc1.w;
            yp += __shfl_xor_sync(0xffffffffu, yp, 1);
            yp += __shfl_xor_sync(0xffffffffu, yp, 2);
            yp += __shfl_xor_sync(0xffffffffu, yp, 4);
            if (ng == 0)
                g_y[(baseRow + t0 + q) * DI + h * HD + p] = yp + Dh * xp;
        }
        __syncthreads();
    }
    // store chunk end-state and product
    size_t so = ((((size_t)(b * NH + h)) * TCH + c) * HD + p) * DSTATE + n0;
    *(float4*)&g_S[so]     = make_float4(s[0], s[1], s[2], s[3]);
    *(float4*)&g_S[so + 4] = make_float4(s[4], s[5], s[6], s[7]);
    if (tid == 0) g_P[(b * NH + h) * TCH + c] = approd;
}

// ---------------- chunked scan: phase B (boundary states) --------------------
__global__ void k_scanB() {
    int idx = blockIdx.x * blockDim.x + threadIdx.x;   // [b][h][p][n]
    if (idx >= B_SZ * NH * HD * DSTATE) return;
    int bh = idx >> 13;                                // b*NH+h
    float H = 0.f;
#pragma unroll 1
    for (int c = 0; c < TCH; c++) {
        size_t o = (((size_t)bh * TCH + c) << 13) + (idx & 8191);
        g_Hb[o] = H;
        H = g_P[bh * TCH + c] * H + g_S[o];
    }
}

// ---------------- chunked scan: phase C (cross-chunk correction) -------------
__global__ void k_scanC() {
    __shared__ float sC[64][64];
    __shared__ float sdA[64];
    int c = (blockIdx.x >> 2) + 1, pblk = blockIdx.x & 3;
    int h = blockIdx.y, b = blockIdx.z;
    int tid = threadIdx.x;
    int pl = tid >> 3, ng = tid & 7, n0 = ng * 8;
    int p = pblk * 32 + pl;
    size_t baseRow = (size_t)b * SEQ;
    // load boundary state entering chunk c
    size_t ho = ((((size_t)(b * NH + h)) * TCH + c) * HD + p) * DSTATE + n0;
    float4 H0 = *(const float4*)&g_Hb[ho];
    float4 H1 = *(const float4*)&g_Hb[ho + 4];
    float ap = 1.f;
    int t0base = c * LCH;
    int tlim = min(SEQ, t0base + LCH);
    for (int t0 = t0base; t0 < tlim; t0 += 64) {
        int cnt = min(64, tlim - t0);
        for (int i = tid; i < cnt * 16; i += 256) {
            int q = i >> 4, ii = i & 15;
            ((float4*)sC[q])[ii] =
                *(const float4*)&g_xBC[(baseRow + t0 + q) * CONV_DIM + DI + DSTATE + ii * 4];
        }
        for (int i = tid; i < cnt; i += 256)
            sdA[i] = g_dA[(baseRow + t0 + i) * NH + h];
        __syncthreads();
        for (int q = 0; q < cnt; q++) {
            ap *= sdA[q];
            if (ap < 1e-37f) { ap = 0.f; break; }
            float4 cc0 = *(const float4*)&sC[q][n0];
            float4 cc1 = *(const float4*)&sC[q][n0 + 4];
            float d = H0.x * cc0.x + H0.y * cc0.y + H0.z * cc0.z + H0.w * cc0.w
                    + H1.x * cc1.x + H1.y * cc1.y + H1.z * cc1.z + H1.w * cc1.w;
            d += __shfl_xor_sync(0xffffffffu, d, 1);
            d += __shfl_xor_sync(0xffffffffu, d, 2);
            d += __shfl_xor_sync(0xffffffffu, d, 4);
            if (ng == 0)
                g_y[(baseRow + t0 + q) * DI + h * HD + p] += ap * d;
        }
        __syncthreads();
        if (ap == 0.f) break;
    }
}

// ---------------- gate + RMSNorm -> bf16 hi/lo --------------------------------
__global__ void k_gaterms(const float* __restrict__ rmsw) {
    __shared__ float red8[8];
    int row = blockIdx.x, tid = threadIdx.x;
    const float4* zr = (const float4*)(g_zx + (size_t)row * DIP);
    const float4* yr = (const float4*)(g_y + (size_t)row * DI);
    float4 z0 = zr[tid], z1 = zr[tid + 256];
    float4 y0 = yr[tid], y1 = yr[tid + 256];
    float4 g0, g1;
    g0.x = y0.x * siluf(z0.x); g0.y = y0.y * siluf(z0.y);
    g0.z = y0.z * siluf(z0.z); g0.w = y0.w * siluf(z0.w);
    g1.x = y1.x * siluf(z1.x); g1.y = y1.y * siluf(z1.y);
    g1.z = y1.z * siluf(z1.z); g1.w = y1.w * siluf(z1.w);
    float ss = g0.x * g0.x + g0.y * g0.y + g0.z * g0.z + g0.w * g0.w
             + g1.x * g1.x + g1.y * g1.y + g1.z * g1.z + g1.w * g1.w;
    float tot = blockSum256(ss, red8);
    float inv = rsqrtf(tot * (1.f / DI) + 1e-5f);
    float4 w0 = ((const float4*)rmsw)[tid], w1 = ((const float4*)rmsw)[tid + 256];
    g0.x *= inv * w0.x; g0.y *= inv * w0.y; g0.z *= inv * w0.z; g0.w *= inv * w0.w;
    g1.x *= inv * w1.x; g1.y *= inv * w1.y; g1.z *= inv * w1.z; g1.w *= inv * w1.w;
    uint32_t h0, l0, h1, l1;
    size_t o = (size_t)row * (DI / 4) + tid;
    bf16split2(g0.x, g0.y, h0, l0);
    bf16split2(g0.z, g0.w, h1, l1);
    ((uint2*)g_yh)[o] = make_uint2(h0, h1);
    ((uint2*)g_yl)[o] = make_uint2(l0, l1);
    bf16split2(g1.x, g1.y, h0, l0);
    bf16split2(g1.z, g1.w, h1, l1);
    ((uint2*)g_yh)[o + 256] = make_uint2(h0, h1);
    ((uint2*)g_yl)[o + 256] = make_uint2(l0, l1);
}

// ---------------- output head: warp per pixel --------------------------------
__global__ void k_head(const float* __restrict__ w, const float* __restrict__ bias,
                       const float* __restrict__ im64, float* __restrict__ out,
                       int out_size) {
    __shared__ float sw[DM * 3];
    int tid = threadIdx.x;
    for (int i = tid; i < DM * 3; i += 256) sw[i] = w[i];
    __syncthreads();
    int lane = tid & 31, wid = tid >> 5;
    int r = blockIdx.x * 8 + wid;
    int b = r / 4096, p = r % 4096;
    const float* xr = g_x + ((size_t)(b * SEQ) + 66 + p) * DM;
    float a0 = 0.f, a1 = 0.f, a2 = 0.f;
    for (int i = lane; i < DM; i += 32) {
        float v = xr[i];
        a0 += v * sw[i * 3 + 0];
        a1 += v * sw[i * 3 + 1];
        a2 += v * sw[i * 3 + 2];
    }
#pragma unroll
    for (int o = 16; o; o >>= 1) {
        a0 += __shfl_xor_sync(0xffffffffu, a0, o);
        a1 += __shfl_xor_sync(0xffffffffu, a1, o);
        a2 += __shfl_xor_sync(0xffffffffu, a2, o);
    }
    if (lane == 0) {
        float y0 = a0 + bias[0], y1 = a1 + bias[1], y2 = a2 + bias[2];
        const float* im = im64 + (size_t)r * 3;
        float e0 = y0 - im[0], e1 = y1 - im[1], e2 = y2 - im[2];
        g_part[r] = e0 * e0 + e1 * e1 + e2 * e2;
        if (out_size >= YHAT_ELEMS) {
            out[(size_t)r * 3 + 0] = y0;
            out[(size_t)r * 3 + 1] = y1;
            out[(size_t)r * 3 + 2] = y2;
        }
    }
}

__global__ void k_loss(float* __restrict__ out, int out_size) {
    __shared__ float red8[8];
    float s = 0.f;
    for (int i = threadIdx.x; i < NPIX; i += 256) s += g_part[i];
    float tot = blockSum256(s, red8);
    if (threadIdx.x == 0) {
        float loss = tot * (1.f / (float)YHAT_ELEMS);
        if (out_size <= 1) out[0] = loss;
        else if (out_size > YHAT_ELEMS) out[YHAT_ELEMS] = loss;
    }
}

// ---------------- driver -----------------------------------------------------
extern "C" void kernel_launch(void* const* d_in, const int* in_sizes, int n_in,
                              void* d_out, int out_size) {
    const float* im8        = (const float*)d_in[0];
    const float* im64       = (const float*)d_in[1];
    const float* from_rgb_w = (const float*)d_in[2];
    const float* from_rgb_b = (const float*)d_in[3];
    const float* to_rgb_w   = (const float*)d_in[4];
    const float* to_rgb_b   = (const float*)d_in[5];
    const float* s0         = (const float*)d_in[6];
    const float* s1         = (const float*)d_in[7];
    const float* posemb     = (const float*)d_in[8];
    const float* ln_w       = (const float*)d_in[9];
    const float* ln_b       = (const float*)d_in[10];
    const float* in_proj_w  = (const float*)d_in[11];
    const float* conv_w     = (const float*)d_in[12];
    const float* conv_b     = (const float*)d_in[13];
    const float* dt_bias    = (const float*)d_in[14];
    const float* A_log      = (const float*)d_in[15];
    const float* Dp         = (const float*)d_in[16];
    const float* rms_w      = (const float*)d_in[17];
    const float* out_proj_w = (const float*)d_in[18];
    float* out = (float*)d_out;

    float *p_x, *p_zx;
    cudaGetSymbolAddress((void**)&p_x, g_x);
    cudaGetSymbolAddress((void**)&p_zx, g_zx);
    __nv_bfloat16 *p_lnh, *p_lnl, *p_yh, *p_yl, *p_w1h, *p_w1l, *p_w2h, *p_w2l;
    cudaGetSymbolAddress((void**)&p_lnh, g_lnh);
    cudaGetSymbolAddress((void**)&p_lnl, g_lnl);
    cudaGetSymbolAddress((void**)&p_yh, g_yh);
    cudaGetSymbolAddress((void**)&p_yl, g_yl);
    cudaGetSymbolAddress((void**)&p_w1h, g_w1h);
    cudaGetSymbolAddress((void**)&p_w1l, g_w1l);
    cudaGetSymbolAddress((void**)&p_w2h, g_w2h);
    cudaGetSymbolAddress((void**)&p_w2l, g_w2l);

    cudaFuncSetAttribute(k_gemm_bs, cudaFuncAttributeMaxDynamicSharedMemorySize,
                         GSMEM);

    {
        int n1 = NL * DIP * DM;
        k_wsplit<<<(n1 / 2 + 255) / 256, 256>>>(in_proj_w, p_w1h, p_w1l, n1);
        int n2 = NL * DM * DI;
        k_wsplit<<<(n2 / 2 + 255) / 256, 256>>>(out_proj_w, p_w2h, p_w2l, n2);
    }

    k_h8<<<(B_SZ * 64 * DM + 255) / 256, 256>>>(im8, from_rgb_w, from_rgb_b);
    k_assemble<<<(MR * DM + 255) / 256, 256>>>(s0, s1, posemb);

    for (int l = 0; l < NL; l++) {
        k_ln<<<MR, 256>>>(ln_w + l * DM, ln_b + l * DM);

        dim3 g1((DIP + BNT - 1) / BNT, (MR + BMT - 1) / BMT);
        k_gemm_bs<<<g1, 256, GSMEM>>>(p_lnh, p_lnl,
                                      p_w1h + (size_t)l * DIP * DM,
                                      p_w1l + (size_t)l * DIP * DM,
                                      p_zx, MR, DIP, DM, 0);

        k_dt<<<(MR * NH + 255) / 256, 256>>>(dt_bias + l * NH, A_log + l * NH);
        k_conv<<<(MR * (CONV_DIM / 4) + 255) / 256, 256>>>(conv_w + l * CONV_DIM * 4,
                                                           conv_b + l * CONV_DIM);

        dim3 gA(TCH * 4, NH, B_SZ);
        k_scanA<<<gA, 256>>>(Dp + l * NH);
        k_scanB<<<(B_SZ * NH * HD * DSTATE + 255) / 256, 256>>>();
        dim3 gC((TCH - 1) * 4, NH, B_SZ);
        k_scanC<<<gC, 256>>>();

        k_gaterms<<<MR, 256>>>(rms_w + l * DI);

        dim3 g2((DM + BNT - 1) / BNT, (MR + BMT - 1) / BMT);
        k_gemm_bs<<<g2, 256, GSMEM>>>(p_yh, p_yl,
                                      p_w2h + (size_t)l * DM * DI,
                                      p_w2l + (size_t)l * DM * DI,
                                      p_x, MR, DM, DI, 1);
    }

    k_head<<<NPIX / 8, 256>>>(to_rgb_w, to_rgb_b, im64, out, out_size);
    k_loss<<<1, 256>>>(out, out_size);
}

// round 9
// speedup vs baseline: 3.2609x; 1.0205x over previous
#include <cuda_runtime.h>
#include <cuda_bf16.h>
#include <math.h>
#include <stdint.h>

#define B_SZ 2
#define SEQ 4162
#define DM 1024
#define DI 2048
#define DSTATE 64
#define HD 128
#define NH 16
#define NL 4
#define CONV_DIM 2176
#define DIP 4240
#define MR (B_SZ*SEQ)          // 8324 rows
#define NPIX (B_SZ*4096)       // 8192
#define YHAT_ELEMS (NPIX*3)    // 24576
#define LCH 256                // scan chunk length
#define TCH 17                 // ceil(SEQ/LCH)

// ---------------- scratch (static device allocations; no cudaMalloc) -------
__device__ float g_x[(size_t)MR*DM];        // residual stream
__device__ float g_zx[(size_t)MR*DIP];      // in_proj output
__device__ float g_xBC[(size_t)MR*CONV_DIM];// conv+silu output
__device__ float g_y[(size_t)MR*DI];        // scan output
__device__ float g_dt[MR*NH];
__device__ float g_dA[MR*NH];
__device__ float g_part[NPIX];
// chunked-scan state buffers
__device__ float g_S[(size_t)B_SZ*NH*TCH*HD*DSTATE];
__device__ float g_Hb[(size_t)B_SZ*NH*TCH*HD*DSTATE];
__device__ float g_P[B_SZ*NH*TCH];
// bf16 hi/lo split buffers
__device__ __nv_bfloat16 g_lnh[(size_t)MR*DM];
__device__ __nv_bfloat16 g_lnl[(size_t)MR*DM];
__device__ __nv_bfloat16 g_yh[(size_t)MR*DI];
__device__ __nv_bfloat16 g_yl[(size_t)MR*DI];
__device__ __nv_bfloat16 g_w1h[(size_t)NL*DIP*DM];
__device__ __nv_bfloat16 g_w1l[(size_t)NL*DIP*DM];
__device__ __nv_bfloat16 g_w2h[(size_t)NL*DM*DI];
__device__ __nv_bfloat16 g_w2l[(size_t)NL*DM*DI];

// ---------------- helpers ---------------------------------------------------
__device__ __forceinline__ float siluf(float x) { return x / (1.f + expf(-x)); }

__device__ __forceinline__ float blockSum256(float v, float* red8) {
    int lane = threadIdx.x & 31, wid = threadIdx.x >> 5;
#pragma unroll
    for (int o = 16; o; o >>= 1) v += __shfl_xor_sync(0xffffffffu, v, o);
    if (lane == 0) red8[wid] = v;
    __syncthreads();
    float r = 0.f;
#pragma unroll
    for (int i = 0; i < 8; i++) r += red8[i];
    __syncthreads();
    return r;
}

__device__ __forceinline__ void bf16split2(float x, float y, uint32_t& hi, uint32_t& lo) {
    __nv_bfloat162 h = __floats2bfloat162_rn(x, y);
    uint32_t hw = *reinterpret_cast<uint32_t*>(&h);
    float hx = __uint_as_float(hw << 16);
    float hy = __uint_as_float(hw & 0xffff0000u);
    __nv_bfloat162 l = __floats2bfloat162_rn(x - hx, y - hy);
    hi = hw;
    lo = *reinterpret_cast<uint32_t*>(&l);
}

__device__ __forceinline__ uint32_t smem_u32(const void* p) {
    uint32_t a;
    asm("{ .reg .u64 t; cvta.to.shared.u64 t, %1; cvt.u32.u64 %0, t; }"
        : "=r"(a) : "l"(p));
    return a;
}

__device__ __forceinline__ void ldsm4(uint32_t a, uint32_t& r0, uint32_t& r1,
                                      uint32_t& r2, uint32_t& r3) {
    asm volatile("ldmatrix.sync.aligned.m8n8.x4.shared.b16 {%0,%1,%2,%3}, [%4];"
                 : "=r"(r0), "=r"(r1), "=r"(r2), "=r"(r3) : "r"(a));
}

__device__ __forceinline__ void cp16(uint32_t dst, const void* src, bool v) {
    int sz = v ? 16 : 0;
    asm volatile("cp.async.ca.shared.global [%0], [%1], 16, %2;"
                 :: "r"(dst), "l"(src), "r"(sz));
}

// ---------------- fused weight split (both projections, one launch) ---------
__global__ void k_wsplit2(const float* __restrict__ w1, const float* __restrict__ w2,
                          __nv_bfloat16* __restrict__ h1, __nv_bfloat16* __restrict__ l1,
                          __nv_bfloat16* __restrict__ h2, __nv_bfloat16* __restrict__ l2,
                          int n1, int n2) {
    int i = blockIdx.x * blockDim.x + threadIdx.x;
    int half1 = n1 / 2;
    if (i < half1) {
        float2 v = ((const float2*)w1)[i];
        uint32_t hi, lo;
        bf16split2(v.x, v.y, hi, lo);
        ((uint32_t*)h1)[i] = hi;
        ((uint32_t*)l1)[i] = lo;
    } else {
        int j = i - half1;
        if (j >= n2 / 2) return;
        float2 v = ((const float2*)w2)[j];
        uint32_t hi, lo;
        bf16split2(v.x, v.y, hi, lo);
        ((uint32_t*)h2)[j] = hi;
        ((uint32_t*)l2)[j] = lo;
    }
}

// ---------------- fused embed (h8 + assemble) --------------------------------
__global__ void k_embed(const float* __restrict__ im8, const float* __restrict__ w,
                        const float* __restrict__ fb,
                        const float* __restrict__ s0, const float* __restrict__ s1,
                        const float* __restrict__ posemb) {
    int idx = blockIdx.x * blockDim.x + threadIdx.x;
    if (idx >= MR * DM) return;
    int d = idx % DM;
    int t = (idx / DM) % SEQ;
    int b = idx / (DM * SEQ);
    float v;
    if (t == 0) v = s0[d];
    else if (t == 65) v = s1[d];
    else {
        int src;
        int p = t - 66;
        if (t <= 64) src = t - 1;
        else src = ((p >> 6) >> 3) * 8 + ((p & 63) >> 3);
        const float* pix = im8 + (b * 64 + src) * 3;
        v = pix[0] * w[d] + pix[1] * w[DM + d] + pix[2] * w[2 * DM + d] + fb[d];
        if (t >= 66) v += posemb[(size_t)p * DM + d];
    }
    g_x[idx] = v;
}

// ---------------- layernorm -> bf16 hi/lo ------------------------------------
__global__ void k_ln(const float* __restrict__ lnw, const float* __restrict__ lnb) {
    __shared__ float red8[8];
    int row = blockIdx.x, tid = threadIdx.x;
    const float4* xr = (const float4*)(g_x + (size_t)row * DM);
    float4 v = xr[tid];
    float mean = blockSum256(v.x + v.y + v.z + v.w, red8) * (1.f / DM);
    float dx = v.x - mean, dy = v.y - mean, dz = v.z - mean, dw = v.w - mean;
    float var = blockSum256(dx * dx + dy * dy + dz * dz + dw * dw, red8) * (1.f / DM);
    float inv = rsqrtf(var + 1e-5f);
    float4 w4 = ((const float4*)lnw)[tid];
    float4 b4 = ((const float4*)lnb)[tid];
    float ox = dx * inv * w4.x + b4.x;
    float oy = dy * inv * w4.y + b4.y;
    float oz = dz * inv * w4.z + b4.z;
    float ow = dw * inv * w4.w + b4.w;
    uint32_t h0, l0, h1, l1;
    bf16split2(ox, oy, h0, l0);
    bf16split2(oz, ow, h1, l1);
    size_t o = (size_t)row * (DM / 4) + tid;
    ((uint2*)g_lnh)[o] = make_uint2(h0, h1);
    ((uint2*)g_lnl)[o] = make_uint2(l0, l1);
}

// ---------------- tensor-core GEMM (pre-split bf16x3 + cp.async) -------------
#define BMT 128
#define BNT 128
#define BK2 32
#define RPITCH 80
#define ARRB (BMT * RPITCH)
#define STAGEB (4 * ARRB)
#define GSMEM (2 * STAGEB)

__global__ void __launch_bounds__(256, 2)
k_gemm_bs(const __nv_bfloat16* __restrict__ Ah, const __nv_bfloat16* __restrict__ Al,
          const __nv_bfloat16* __restrict__ Bh, const __nv_bfloat16* __restrict__ Bl,
          float* __restrict__ C, int M, int N, int K, int accum) {
    extern __shared__ char smem[];
    const uint32_t sb = smem_u32(smem);
    const int tid = threadIdx.x;
    const int lane = tid & 31;
    const int wid = tid >> 5;
    const int warpM = wid >> 1;
    const int warpN = wid & 1;
    const int row0 = blockIdx.y * BMT;
    const int col0 = blockIdx.x * BNT;

    const int lr = lane >> 2, lc = lane & 3;
    const int grp = lane >> 3, lrow = lane & 7;
    const int a_mrow = (grp & 1) * 8 + lrow;
    const int a_koff = (grp >> 1) * 16;
    const int b_nrow = (grp >> 1) * 8 + lrow;
    const int b_koff = (grp & 1) * 16;

    float acc[2][8][4];
#pragma unroll
    for (int mt = 0; mt < 2; mt++)
#pragma unroll
        for (int nt = 0; nt < 8; nt++)
#pragma unroll
            for (int r = 0; r < 4; r++) acc[mt][nt][r] = 0.f;

    const int ntiles = K / BK2;
    const int ch0 = tid, ch1 = tid + 256;
    const int r0 = ch0 >> 2, c0 = ch0 & 3;
    const int r1 = ch1 >> 2, c1 = ch1 & 3;

    auto issue_stage = [&](int t, int buf) {
        int k0 = t * BK2;
        uint32_t s0 = sb + buf * STAGEB;
#pragma unroll
        for (int u = 0; u < 2; u++) {
            int r = u ? r1 : r0;
            int c = u ? c1 : c0;
            uint32_t doff = r * RPITCH + c * 16;
            int gra = row0 + r;
            bool va = gra < M;
            int grac = va ? gra : 0;
            size_t aoff = (size_t)grac * K + k0 + c * 8;
            cp16(s0 + doff, Ah + aoff, va);
            cp16(s0 + ARRB + doff, Al + aoff, va);
            int grb = col0 + r;
            bool vb = grb < N;
            int grbc = vb ? grb : 0;
            size_t boff = (size_t)grbc * K + k0 + c * 8;
            cp16(s0 + 2 * ARRB + doff, Bh + boff, vb);
            cp16(s0 + 3 * ARRB + doff, Bl + boff, vb);
        }
        asm volatile("cp.async.commit_group;");
    };

    issue_stage(0, 0);
    if (ntiles > 1) issue_stage(1, 1);
    else asm volatile("cp.async.commit_group;");

    for (int t = 0; t < ntiles; t++) {
        int buf = t & 1;
        if (t + 2 < ntiles) asm volatile("cp.async.wait_group 1;");
        else asm volatile("cp.async.wait_group 0;");
        __syncthreads();

        uint32_t sstage = sb + buf * STAGEB;
#pragma unroll
        for (int ks = 0; ks < 2; ks++) {
            uint32_t ah[2][4], al[2][4];
#pragma unroll
            for (int mt = 0; mt < 2; mt++) {
                uint32_t aoff = sstage + (warpM * 32 + mt * 16 + a_mrow) * RPITCH
                                + a_koff + ks * 32;
                ldsm4(aoff, ah[mt][0], ah[mt][1], ah[mt][2], ah[mt][3]);
                ldsm4(aoff + ARRB, al[mt][0], al[mt][1], al[mt][2], al[mt][3]);
            }
#pragma unroll
            for (int ntp = 0; ntp < 4; ntp++) {
                uint32_t boff = sstage + 2 * ARRB
                                + (warpN * 64 + ntp * 16 + b_nrow) * RPITCH
                                + b_koff + ks * 32;
                uint32_t bh[4], bl[4];
                ldsm4(boff, bh[0], bh[1], bh[2], bh[3]);
                ldsm4(boff + ARRB, bl[0], bl[1], bl[2], bl[3]);
#pragma unroll
                for (int par = 0; par < 2; par++) {
                    int nt = ntp * 2 + par;
                    uint32_t b0h = bh[par * 2], b1h = bh[par * 2 + 1];
                    uint32_t b0l = bl[par * 2], b1l = bl[par * 2 + 1];
#pragma unroll
                    for (int mt = 0; mt < 2; mt++) {
                        asm volatile(
                            "mma.sync.aligned.m16n8k16.row.col.f32.bf16.bf16.f32 "
                            "{%0,%1,%2,%3}, {%4,%5,%6,%7}, {%8,%9}, {%0,%1,%2,%3};"
                            : "+f"(acc[mt][nt][0]), "+f"(acc[mt][nt][1]),
                              "+f"(acc[mt][nt][2]), "+f"(acc[mt][nt][3])
                            : "r"(al[mt][0]), "r"(al[mt][1]), "r"(al[mt][2]), "r"(al[mt][3]),
                              "r"(b0h), "r"(b1h));
                        asm volatile(
                            "mma.sync.aligned.m16n8k16.row.col.f32.bf16.bf16.f32 "
                            "{%0,%1,%2,%3}, {%4,%5,%6,%7}, {%8,%9}, {%0,%1,%2,%3};"
                            : "+f"(acc[mt][nt][0]), "+f"(acc[mt][nt][1]),
                              "+f"(acc[mt][nt][2]), "+f"(acc[mt][nt][3])
                            : "r"(ah[mt][0]), "r"(ah[mt][1]), "r"(ah[mt][2]), "r"(ah[mt][3]),
                              "r"(b0l), "r"(b1l));
                        asm volatile(
                            "mma.sync.aligned.m16n8k16.row.col.f32.bf16.bf16.f32 "
                            "{%0,%1,%2,%3}, {%4,%5,%6,%7}, {%8,%9}, {%0,%1,%2,%3};"
                            : "+f"(acc[mt][nt][0]), "+f"(acc[mt][nt][1]),
                              "+f"(acc[mt][nt][2]), "+f"(acc[mt][nt][3])
                            : "r"(ah[mt][0]), "r"(ah[mt][1]), "r"(ah[mt][2]), "r"(ah[mt][3]),
                              "r"(b0h), "r"(b1h));
                    }
                }
            }
        }
        __syncthreads();
        if (t + 2 < ntiles) issue_stage(t + 2, buf);
    }

#pragma unroll
    for (int mt = 0; mt < 2; mt++) {
        int rbase = row0 + warpM * 32 + mt * 16 + lr;
#pragma unroll
        for (int nt = 0; nt < 8; nt++) {
            int cbase = col0 + warpN * 64 + nt * 8 + lc * 2;
            if (rbase < M) {
                if (cbase < N) {
                    size_t o = (size_t)rbase * N + cbase;
                    C[o] = accum ? (C[o] + acc[mt][nt][0]) : acc[mt][nt][0];
                }
                if (cbase + 1 < N) {
                    size_t o = (size_t)rbase * N + cbase + 1;
                    C[o] = accum ? (C[o] + acc[mt][nt][1]) : acc[mt][nt][1];
                }
            }
            if (rbase + 8 < M) {
                if (cbase < N) {
                    size_t o = (size_t)(rbase + 8) * N + cbase;
                    C[o] = accum ? (C[o] + acc[mt][nt][2]) : acc[mt][nt][2];
                }
                if (cbase + 1 < N) {
                    size_t o = (size_t)(rbase + 8) * N + cbase + 1;
                    C[o] = accum ? (C[o] + acc[mt][nt][3]) : acc[mt][nt][3];
                }
            }
        }
    }
}

// ---------------- dt / dA ---------------------------------------------------
__global__ void k_dt(const float* __restrict__ dtb, const float* __restrict__ Alog) {
    int idx = blockIdx.x * blockDim.x + threadIdx.x;
    if (idx >= MR * NH) return;
    int h = idx % NH;
    int row = idx / NH;
    float v = g_zx[(size_t)row * DIP + (DIP - NH) + h] + dtb[h];
    float sp = (v > 20.f) ? v : log1pf(expf(v));
    float A = -expf(Alog[h]);
    g_dt[idx] = sp;
    g_dA[idx] = expf(sp * A);
}

// ---------------- causal depthwise conv: smem-tiled (64t x 64ch) -------------
#define CTS 64
#define CCS 64
__global__ void k_conv(const float* __restrict__ cw, const float* __restrict__ cb) {
    __shared__ float st[CTS + 3][CCS];
    int c0 = blockIdx.x * CCS;
    int t0 = blockIdx.y * CTS;
    int b = blockIdx.z;
    int tid = threadIdx.x;
    // stage rows t0-3 .. t0+CTS-1
    for (int i = tid; i < (CTS + 3) * (CCS / 4); i += 256) {
        int rr = i >> 4, cc = (i & 15) * 4;
        int t = t0 - 3 + rr;
        float4 v = make_float4(0.f, 0.f, 0.f, 0.f);
        if (t >= 0 && t < SEQ)
            v = *(const float4*)&g_zx[((size_t)(b * SEQ + t)) * DIP + DI + c0 + cc];
        *(float4*)&st[rr][cc] = v;
    }
    __syncthreads();
    int cc = (tid & 15) * 4;
    int tt = (tid >> 4) * 4;
    float4 w0 = *(const float4*)(cw + (c0 + cc) * 4);
    float4 w1 = *(const float4*)(cw + (c0 + cc + 1) * 4);
    float4 w2 = *(const float4*)(cw + (c0 + cc + 2) * 4);
    float4 w3 = *(const float4*)(cw + (c0 + cc + 3) * 4);
    float4 bias = *(const float4*)(cb + c0 + cc);
#pragma unroll
    for (int u = 0; u < 4; u++) {
        int t = t0 + tt + u;
        if (t >= SEQ) break;
        float4 xv0 = *(const float4*)&st[tt + u + 0][cc];
        float4 xv1 = *(const float4*)&st[tt + u + 1][cc];
        float4 xv2 = *(const float4*)&st[tt + u + 2][cc];
        float4 xv3 = *(const float4*)&st[tt + u + 3][cc];
        float4 acc = bias;
        acc.x += xv0.x * w0.x + xv1.x * w0.y + xv2.x * w0.z + xv3.x * w0.w;
        acc.y += xv0.y * w1.x + xv1.y * w1.y + xv2.y * w1.z + xv3.y * w1.w;
        acc.z += xv0.z * w2.x + xv1.z * w2.y + xv2.z * w2.z + xv3.z * w2.w;
        acc.w += xv0.w * w3.x + xv1.w * w3.y + xv2.w * w3.z + xv3.w * w3.w;
        float4 o = make_float4(siluf(acc.x), siluf(acc.y), siluf(acc.z), siluf(acc.w));
        *(float4*)&g_xBC[((size_t)(b * SEQ + t)) * CONV_DIM + c0 + cc] = o;
    }
}

// ---------------- chunked scan: phase A (local scans) ------------------------
__global__ void k_scanA(const float* __restrict__ Dp) {
    __shared__ float sx[64][32];
    __shared__ float sB[64][64];
    __shared__ float sC[64][64];
    __shared__ float sdA[64];
    __shared__ float sdt[64];
    int c = blockIdx.x >> 2, pblk = blockIdx.x & 3;
    int h = blockIdx.y, b = blockIdx.z;
    int tid = threadIdx.x;
    int pl = tid >> 3, ng = tid & 7, n0 = ng * 8;
    int p = pblk * 32 + pl;
    float s[8];
#pragma unroll
    for (int j = 0; j < 8; j++) s[j] = 0.f;
    float approd = 1.f;
    float Dh = Dp[h];
    size_t baseRow = (size_t)b * SEQ;
    int xoff = h * HD + pblk * 32;
    int t0base = c * LCH;
    int tlim = min(SEQ, t0base + LCH);
    for (int t0 = t0base; t0 < tlim; t0 += 64) {
        int cnt = min(64, tlim - t0);
        for (int i = tid; i < cnt * 8; i += 256) {
            int q = i >> 3, ii = i & 7;
            ((float4*)sx[q])[ii] =
                *(const float4*)&g_xBC[(baseRow + t0 + q) * CONV_DIM + xoff + ii * 4];
        }
        for (int i = tid; i < cnt * 16; i += 256) {
            int q = i >> 4, ii = i & 15;
            ((float4*)sB[q])[ii] =
                *(const float4*)&g_xBC[(baseRow + t0 + q) * CONV_DIM + DI + ii * 4];
        }
        for (int i = tid; i < cnt * 16; i += 256) {
            int q = i >> 4, ii = i & 15;
            ((float4*)sC[q])[ii] =
                *(const float4*)&g_xBC[(baseRow + t0 + q) * CONV_DIM + DI + DSTATE + ii * 4];
        }
        for (int i = tid; i < cnt; i += 256) {
            sdA[i] = g_dA[(baseRow + t0 + i) * NH + h];
            sdt[i] = g_dt[(baseRow + t0 + i) * NH + h];
        }
        __syncthreads();
        for (int q = 0; q < cnt; q++) {
            float dA = sdA[q];
            approd *= dA;
            float xp = sx[q][pl];
            float a = sdt[q] * xp;
            float4 bb0 = *(const float4*)&sB[q][n0];
            float4 bb1 = *(const float4*)&sB[q][n0 + 4];
            float4 cc0 = *(const float4*)&sC[q][n0];
            float4 cc1 = *(const float4*)&sC[q][n0 + 4];
            float yp;
            s[0] = s[0] * dA + a * bb0.x; yp  = s[0] * cc0.x;
            s[1] = s[1] * dA + a * bb0.y; yp += s[1] * cc0.y;
            s[2] = s[2] * dA + a * bb0.z; yp += s[2] * cc0.z;
            s[3] = s[3] * dA + a * bb0.w; yp += s[3] * cc0.w;
            s[4] = s[4] * dA + a * bb1.x; yp += s[4] * cc1.x;
            s[5] = s[5] * dA + a * bb1.y; yp += s[5] * cc1.y;
            s[6] = s[6] * dA + a * bb1.z; yp += s[6] * cc1.z;
            s[7] = s[7] * dA + a * bb1.w; yp += s[7] * cc1.w;
            yp += __shfl_xor_sync(0xffffffffu, yp, 1);
            yp += __shfl_xor_sync(0xffffffffu, yp, 2);
            yp += __shfl_xor_sync(0xffffffffu, yp, 4);
            if (ng == 0)
                g_y[(baseRow + t0 + q) * DI + h * HD + p] = yp + Dh * xp;
        }
        __syncthreads();
    }
    size_t so = ((((size_t)(b * NH + h)) * TCH + c) * HD + p) * DSTATE + n0;
    *(float4*)&g_S[so]     = make_float4(s[0], s[1], s[2], s[3]);
    *(float4*)&g_S[so + 4] = make_float4(s[4], s[5], s[6], s[7]);
    if (tid == 0) g_P[(b * NH + h) * TCH + c] = approd;
}

// ---------------- chunked scan: phase B (boundary states) --------------------
__global__ void k_scanB() {
    int idx = blockIdx.x * blockDim.x + threadIdx.x;
    if (idx >= B_SZ * NH * HD * DSTATE) return;
    int bh = idx >> 13;
    float H = 0.f;
#pragma unroll 1
    for (int c = 0; c < TCH; c++) {
        size_t o = (((size_t)bh * TCH + c) << 13) + (idx & 8191);
        g_Hb[o] = H;
        H = g_P[bh * TCH + c] * H + g_S[o];
    }
}

// ---------------- chunked scan: phase C (cross-chunk correction) -------------
__global__ void k_scanC() {
    __shared__ float sC[64][64];
    __shared__ float sdA[64];
    int c = (blockIdx.x >> 2) + 1, pblk = blockIdx.x & 3;
    int h = blockIdx.y, b = blockIdx.z;
    int tid = threadIdx.x;
    int pl = tid >> 3, ng = tid & 7, n0 = ng * 8;
    int p = pblk * 32 + pl;
    size_t baseRow = (size_t)b * SEQ;
    size_t ho = ((((size_t)(b * NH + h)) * TCH + c) * HD + p) * DSTATE + n0;
    float4 H0 = *(const float4*)&g_Hb[ho];
    float4 H1 = *(const float4*)&g_Hb[ho + 4];
    float ap = 1.f;
    int t0base = c * LCH;
    int tlim = min(SEQ, t0base + LCH);
    for (int t0 = t0base; t0 < tlim; t0 += 64) {
        int cnt = min(64, tlim - t0);
        for (int i = tid; i < cnt * 16; i += 256) {
            int q = i >> 4, ii = i & 15;
            ((float4*)sC[q])[ii] =
                *(const float4*)&g_xBC[(baseRow + t0 + q) * CONV_DIM + DI + DSTATE + ii * 4];
        }
        for (int i = tid; i < cnt; i += 256)
            sdA[i] = g_dA[(baseRow + t0 + i) * NH + h];
        __syncthreads();
        for (int q = 0; q < cnt; q++) {
            ap *= sdA[q];
            if (ap < 1e-37f) { ap = 0.f; break; }
            float4 cc0 = *(const float4*)&sC[q][n0];
            float4 cc1 = *(const float4*)&sC[q][n0 + 4];
            float d = H0.x * cc0.x + H0.y * cc0.y + H0.z * cc0.z + H0.w * cc0.w
                    + H1.x * cc1.x + H1.y * cc1.y + H1.z * cc1.z + H1.w * cc1.w;
            d += __shfl_xor_sync(0xffffffffu, d, 1);
            d += __shfl_xor_sync(0xffffffffu, d, 2);
            d += __shfl_xor_sync(0xffffffffu, d, 4);
            if (ng == 0)
                g_y[(baseRow + t0 + q) * DI + h * HD + p] += ap * d;
        }
        __syncthreads();
        if (ap == 0.f) break;
    }
}

// ---------------- gate + RMSNorm -> bf16 hi/lo --------------------------------
__global__ void k_gaterms(const float* __restrict__ rmsw) {
    __shared__ float red8[8];
    int row = blockIdx.x, tid = threadIdx.x;
    const float4* zr = (const float4*)(g_zx + (size_t)row * DIP);
    const float4* yr = (const float4*)(g_y + (size_t)row * DI);
    float4 z0 = zr[tid], z1 = zr[tid + 256];
    float4 y0 = yr[tid], y1 = yr[tid + 256];
    float4 g0, g1;
    g0.x = y0.x * siluf(z0.x); g0.y = y0.y * siluf(z0.y);
    g0.z = y0.z * siluf(z0.z); g0.w = y0.w * siluf(z0.w);
    g1.x = y1.x * siluf(z1.x); g1.y = y1.y * siluf(z1.y);
    g1.z = y1.z * siluf(z1.z); g1.w = y1.w * siluf(z1.w);
    float ss = g0.x * g0.x + g0.y * g0.y + g0.z * g0.z + g0.w * g0.w
             + g1.x * g1.x + g1.y * g1.y + g1.z * g1.z + g1.w * g1.w;
    float tot = blockSum256(ss, red8);
    float inv = rsqrtf(tot * (1.f / DI) + 1e-5f);
    float4 w0 = ((const float4*)rmsw)[tid], w1 = ((const float4*)rmsw)[tid + 256];
    g0.x *= inv * w0.x; g0.y *= inv * w0.y; g0.z *= inv * w0.z; g0.w *= inv * w0.w;
    g1.x *= inv * w1.x; g1.y *= inv * w1.y; g1.z *= inv * w1.z; g1.w *= inv * w1.w;
    uint32_t h0, l0, h1, l1;
    size_t o = (size_t)row * (DI / 4) + tid;
    bf16split2(g0.x, g0.y, h0, l0);
    bf16split2(g0.z, g0.w, h1, l1);
    ((uint2*)g_yh)[o] = make_uint2(h0, h1);
    ((uint2*)g_yl)[o] = make_uint2(l0, l1);
    bf16split2(g1.x, g1.y, h0, l0);
    bf16split2(g1.z, g1.w, h1, l1);
    ((uint2*)g_yh)[o + 256] = make_uint2(h0, h1);
    ((uint2*)g_yl)[o + 256] = make_uint2(l0, l1);
}

// ---------------- output head: warp per pixel --------------------------------
__global__ void k_head(const float* __restrict__ w, const float* __restrict__ bias,
                       const float* __restrict__ im64, float* __restrict__ out,
                       int out_size) {
    __shared__ float sw[DM * 3];
    int tid = threadIdx.x;
    for (int i = tid; i < DM * 3; i += 256) sw[i] = w[i];
    __syncthreads();
    int lane = tid & 31, wid = tid >> 5;
    int r = blockIdx.x * 8 + wid;
    int b = r / 4096, p = r % 4096;
    const float* xr = g_x + ((size_t)(b * SEQ) + 66 + p) * DM;
    float a0 = 0.f, a1 = 0.f, a2 = 0.f;
    for (int i = lane; i < DM; i += 32) {
        float v = xr[i];
        a0 += v * sw[i * 3 + 0];
        a1 += v * sw[i * 3 + 1];
        a2 += v * sw[i * 3 + 2];
    }
#pragma unroll
    for (int o = 16; o; o >>= 1) {
        a0 += __shfl_xor_sync(0xffffffffu, a0, o);
        a1 += __shfl_xor_sync(0xffffffffu, a1, o);
        a2 += __shfl_xor_sync(0xffffffffu, a2, o);
    }
    if (lane == 0) {
        float y0 = a0 + bias[0], y1 = a1 + bias[1], y2 = a2 + bias[2];
        const float* im = im64 + (size_t)r * 3;
        float e0 = y0 - im[0], e1 = y1 - im[1], e2 = y2 - im[2];
        g_part[r] = e0 * e0 + e1 * e1 + e2 * e2;
        if (out_size >= YHAT_ELEMS) {
            out[(size_t)r * 3 + 0] = y0;
            out[(size_t)r * 3 + 1] = y1;
            out[(size_t)r * 3 + 2] = y2;
        }
    }
}

__global__ void k_loss(float* __restrict__ out, int out_size) {
    __shared__ float red8[8];
    float s = 0.f;
    for (int i = threadIdx.x; i < NPIX; i += 256) s += g_part[i];
    float tot = blockSum256(s, red8);
    if (threadIdx.x == 0) {
        float loss = tot * (1.f / (float)YHAT_ELEMS);
        if (out_size <= 1) out[0] = loss;
        else if (out_size > YHAT_ELEMS) out[YHAT_ELEMS] = loss;
    }
}

// ---------------- driver -----------------------------------------------------
extern "C" void kernel_launch(void* const* d_in, const int* in_sizes, int n_in,
                              void* d_out, int out_size) {
    const float* im8        = (const float*)d_in[0];
    const float* im64       = (const float*)d_in[1];
    const float* from_rgb_w = (const float*)d_in[2];
    const float* from_rgb_b = (const float*)d_in[3];
    const float* to_rgb_w   = (const float*)d_in[4];
    const float* to_rgb_b   = (const float*)d_in[5];
    const float* s0         = (const float*)d_in[6];
    const float* s1         = (const float*)d_in[7];
    const float* posemb     = (const float*)d_in[8];
    const float* ln_w       = (const float*)d_in[9];
    const float* ln_b       = (const float*)d_in[10];
    const float* in_proj_w  = (const float*)d_in[11];
    const float* conv_w     = (const float*)d_in[12];
    const float* conv_b     = (const float*)d_in[13];
    const float* dt_bias    = (const float*)d_in[14];
    const float* A_log      = (const float*)d_in[15];
    const float* Dp         = (const float*)d_in[16];
    const float* rms_w      = (const float*)d_in[17];
    const float* out_proj_w = (const float*)d_in[18];
    float* out = (float*)d_out;

    float *p_x, *p_zx;
    cudaGetSymbolAddress((void**)&p_x, g_x);
    cudaGetSymbolAddress((void**)&p_zx, g_zx);
    __nv_bfloat16 *p_lnh, *p_lnl, *p_yh, *p_yl, *p_w1h, *p_w1l, *p_w2h, *p_w2l;
    cudaGetSymbolAddress((void**)&p_lnh, g_lnh);
    cudaGetSymbolAddress((void**)&p_lnl, g_lnl);
    cudaGetSymbolAddress((void**)&p_yh, g_yh);
    cudaGetSymbolAddress((void**)&p_yl, g_yl);
    cudaGetSymbolAddress((void**)&p_w1h, g_w1h);
    cudaGetSymbolAddress((void**)&p_w1l, g_w1l);
    cudaGetSymbolAddress((void**)&p_w2h, g_w2h);
    cudaGetSymbolAddress((void**)&p_w2l, g_w2l);

    cudaFuncSetAttribute(k_gemm_bs, cudaFuncAttributeMaxDynamicSharedMemorySize,
                         GSMEM);

    // launch #1: fused weight split
    {
        int n1 = NL * DIP * DM, n2 = NL * DM * DI;
        int tot = n1 / 2 + n2 / 2;
        k_wsplit2<<<(tot + 255) / 256, 256>>>(in_proj_w, out_proj_w,
                                              p_w1h, p_w1l, p_w2h, p_w2l, n1, n2);
    }
    // launch #2: fused embed
    k_embed<<<(MR * DM + 255) / 256, 256>>>(im8, from_rgb_w, from_rgb_b,
                                            s0, s1, posemb);

    for (int l = 0; l < NL; l++) {
        // launch #3 (first layer): LN ; launch #4: in_proj GEMM (profiled)
        k_ln<<<MR, 256>>>(ln_w + l * DM, ln_b + l * DM);

        dim3 g1((DIP + BNT - 1) / BNT, (MR + BMT - 1) / BMT);
        k_gemm_bs<<<g1, 256, GSMEM>>>(p_lnh, p_lnl,
                                      p_w1h + (size_t)l * DIP * DM,
                                      p_w1l + (size_t)l * DIP * DM,
                                      p_zx, MR, DIP, DM, 0);

        k_dt<<<(MR * NH + 255) / 256, 256>>>(dt_bias + l * NH, A_log + l * NH);
        dim3 gconv(CONV_DIM / CCS, (SEQ + CTS - 1) / CTS, B_SZ);
        k_conv<<<gconv, 256>>>(conv_w + l * CONV_DIM * 4, conv_b + l * CONV_DIM);

        dim3 gA(TCH * 4, NH, B_SZ);
        k_scanA<<<gA, 256>>>(Dp + l * NH);
        k_scanB<<<(B_SZ * NH * HD * DSTATE + 255) / 256, 256>>>();
        dim3 gC((TCH - 1) * 4, NH, B_SZ);
        k_scanC<<<gC, 256>>>();

        k_gaterms<<<MR, 256>>>(rms_w + l * DI);

        dim3 g2((DM + BNT - 1) / BNT, (MR + BMT - 1) / BMT);
        k_gemm_bs<<<g2, 256, GSMEM>>>(p_yh, p_yl,
                                      p_w2h + (size_t)l * DM * DI,
                                      p_w2l + (size_t)l * DM * DI,
                                      p_x, MR, DM, DI, 1);
    }

    k_head<<<NPIX / 8, 256>>>(to_rgb_w, to_rgb_b, im64, out, out_size);
    k_loss<<<1, 256>>>(out, out_size);
}